// round 1
// baseline (speedup 1.0000x reference)
#include <cuda_runtime.h>

#define B_  2
#define T_  1024
#define S_  1024
#define NQ  16
#define NKV 4
#define HD  128

// Scratch (allocation-free rule: __device__ globals)
__device__ float g_q[B_*T_*NQ*HD];      // (B,T,NQ,HD)
__device__ float g_k[B_*S_*NKV*HD];     // (B,S,NKV,HD)
__device__ float g_v[B_*S_*NKV*HD];
__device__ float g_attn[B_*T_*NQ*HD];

// ---------------- SGEMM: C[M,N] = A[M,K] @ B[K,N], all row-major ----------------
// 128x128 tile, BK=16, 256 threads, 8x8 per thread. M%128==0, N%128==0, K%16==0.
__global__ void __launch_bounds__(256) sgemm128(
    const float* __restrict__ A, const float* __restrict__ B,
    float* __restrict__ C, int M, int N, int K)
{
    __shared__ float As[16][128];   // transposed A tile
    __shared__ float Bs[16][128];
    const int tid = threadIdx.x;
    const int tx = tid & 15, ty = tid >> 4;
    const int row0 = blockIdx.y * 128;
    const int col0 = blockIdx.x * 128;
    float acc[8][8] = {};

    for (int k0 = 0; k0 < K; k0 += 16) {
        #pragma unroll
        for (int i = 0; i < 2; i++) {
            int f = tid + i * 256;
            int r  = f >> 2;
            int c4 = (f & 3) << 2;
            float4 a = *(const float4*)(A + (size_t)(row0 + r) * K + k0 + c4);
            As[c4+0][r] = a.x; As[c4+1][r] = a.y; As[c4+2][r] = a.z; As[c4+3][r] = a.w;
            int rb = f >> 5;
            int cb = (f & 31) << 2;
            *(float4*)&Bs[rb][cb] = *(const float4*)(B + (size_t)(k0 + rb) * N + col0 + cb);
        }
        __syncthreads();
        #pragma unroll
        for (int kk = 0; kk < 16; kk++) {
            float a[8], b[8];
            *(float4*)&a[0] = *(float4*)&As[kk][ty*8];
            *(float4*)&a[4] = *(float4*)&As[kk][ty*8+4];
            *(float4*)&b[0] = *(float4*)&Bs[kk][tx*8];
            *(float4*)&b[4] = *(float4*)&Bs[kk][tx*8+4];
            #pragma unroll
            for (int i = 0; i < 8; i++)
                #pragma unroll
                for (int j = 0; j < 8; j++)
                    acc[i][j] += a[i] * b[j];
        }
        __syncthreads();
    }
    #pragma unroll
    for (int i = 0; i < 8; i++) {
        float* cp = C + (size_t)(row0 + ty*8 + i) * N + col0 + tx*8;
        *(float4*)cp     = make_float4(acc[i][0], acc[i][1], acc[i][2], acc[i][3]);
        *(float4*)(cp+4) = make_float4(acc[i][4], acc[i][5], acc[i][6], acc[i][7]);
    }
}

// ---------------- RoPE (in-place): x (BL, Nh, HD), half = 64 ----------------
__global__ void rope_kernel(float* __restrict__ x, const int* __restrict__ pos,
                            int total, int Nh)
{
    int idx = blockIdx.x * blockDim.x + threadIdx.x;
    if (idx >= total) return;
    int i   = idx & 63;          // 0..63
    int bln = idx >> 6;          // bl*Nh + n
    int bl  = bln / Nh;
    float p    = (float)pos[bl];
    float frac = (float)i * (1.0f / 64.0f);       // 2*i/H
    float ts   = powf(10000.0f, frac);            // MIN_TS=1, MAX_TS=1e4
    float ang  = p / ts;
    float si = sinf(ang), co = cosf(ang);
    float* base = x + (size_t)bln * HD;
    float x1 = base[i], x2 = base[i + 64];
    base[i]      = x1 * co - x2 * si;
    base[i + 64] = x2 * co + x1 * si;
}

// ---------------- Flash attention: per (b, head, 64-query tile) ----------------
#define PAD 68

__global__ void __launch_bounds__(256) attn_kernel(
    const float* __restrict__ q, const float* __restrict__ k,
    const float* __restrict__ v, float* __restrict__ o)
{
    extern __shared__ float smem[];
    float* Qt = smem;                 // [128][PAD], h-major, cols = 64 query rows
    float* Kt = Qt + 128 * PAD;       // [128][PAD], h-major, cols = 64 key rows
    float* Vs = Kt + 128 * PAD;       // [64][128], row = key, col = h
    float* Ps = Vs + 64 * 128;        // [64][PAD]

    const int tid = threadIdx.x;
    const int tx = tid & 15, ty = tid >> 4;
    const int t0 = blockIdx.x * 64;
    const int n  = blockIdx.y;
    const int b  = blockIdx.z;
    const int kvh = n >> 2;           // G = 4

    const float* Qg = q + ((size_t)(b * T_ + t0) * NQ  + n)   * HD;
    const float* Kg = k + ((size_t)(b * S_)      * NKV + kvh) * HD;
    const float* Vg = v + ((size_t)(b * S_)      * NKV + kvh) * HD;

    // Load Q tile transposed: Qt[h][i]
    for (int f = tid; f < 64 * 32; f += 256) {
        int r  = f >> 5;
        int h4 = (f & 31) << 2;
        float4 a = *(const float4*)(Qg + (size_t)r * (NQ * HD) + h4);
        Qt[(h4+0)*PAD + r] = a.x;
        Qt[(h4+1)*PAD + r] = a.y;
        Qt[(h4+2)*PAD + r] = a.z;
        Qt[(h4+3)*PAD + r] = a.w;
    }

    float m[4], l[4], oa[4][8];
    #pragma unroll
    for (int r = 0; r < 4; r++) {
        m[r] = -1e30f; l[r] = 0.f;
        #pragma unroll
        for (int c = 0; c < 8; c++) oa[r][c] = 0.f;
    }

    for (int s0 = 0; s0 < S_; s0 += 64) {
        __syncthreads();   // previous PV done reading Vs/Ps (also orders Q load on iter 0)
        for (int f = tid; f < 64 * 32; f += 256) {
            int r  = f >> 5;
            int h4 = (f & 31) << 2;
            float4 a = *(const float4*)(Kg + (size_t)(s0 + r) * (NKV * HD) + h4);
            Kt[(h4+0)*PAD + r] = a.x;
            Kt[(h4+1)*PAD + r] = a.y;
            Kt[(h4+2)*PAD + r] = a.z;
            Kt[(h4+3)*PAD + r] = a.w;
            *(float4*)&Vs[r * 128 + h4] = *(const float4*)(Vg + (size_t)(s0 + r) * (NKV * HD) + h4);
        }
        __syncthreads();

        // S = Q K^T  (rows ty*4+r, cols tx*4+c)
        float s[4][4] = {};
        #pragma unroll 8
        for (int h = 0; h < 128; h++) {
            float qv[4], kv[4];
            *(float4*)qv = *(float4*)&Qt[h * PAD + ty * 4];
            *(float4*)kv = *(float4*)&Kt[h * PAD + tx * 4];
            #pragma unroll
            for (int r = 0; r < 4; r++)
                #pragma unroll
                for (int c = 0; c < 4; c++)
                    s[r][c] += qv[r] * kv[c];
        }

        // online softmax (row stats reduced over the 16 tx lanes)
        #pragma unroll
        for (int r = 0; r < 4; r++) {
            float mx = fmaxf(fmaxf(s[r][0], s[r][1]), fmaxf(s[r][2], s[r][3]));
            #pragma unroll
            for (int off = 8; off; off >>= 1)
                mx = fmaxf(mx, __shfl_xor_sync(0xffffffffu, mx, off));
            float mnew = fmaxf(m[r], mx);
            float corr = __expf(m[r] - mnew);
            float psum = 0.f;
            #pragma unroll
            for (int c = 0; c < 4; c++) { s[r][c] = __expf(s[r][c] - mnew); psum += s[r][c]; }
            #pragma unroll
            for (int off = 8; off; off >>= 1)
                psum += __shfl_xor_sync(0xffffffffu, psum, off);
            l[r] = l[r] * corr + psum;
            m[r] = mnew;
            #pragma unroll
            for (int c = 0; c < 8; c++) oa[r][c] *= corr;
            *(float4*)&Ps[(ty*4 + r) * PAD + tx*4] = make_float4(s[r][0], s[r][1], s[r][2], s[r][3]);
        }
        __syncthreads();

        // O += P V  (rows ty*4+r, h-cols tx*8..tx*8+7)
        #pragma unroll 4
        for (int j = 0; j < 64; j++) {
            float pv[4], vv[8];
            #pragma unroll
            for (int r = 0; r < 4; r++) pv[r] = Ps[(ty*4 + r) * PAD + j];
            *(float4*)&vv[0] = *(float4*)&Vs[j * 128 + tx*8];
            *(float4*)&vv[4] = *(float4*)&Vs[j * 128 + tx*8 + 4];
            #pragma unroll
            for (int r = 0; r < 4; r++)
                #pragma unroll
                for (int c = 0; c < 8; c++)
                    oa[r][c] += pv[r] * vv[c];
        }
    }

    #pragma unroll
    for (int r = 0; r < 4; r++) {
        float inv = 1.0f / l[r];
        int t = t0 + ty*4 + r;
        float* op = o + ((size_t)(b * T_ + t) * NQ + n) * HD + tx*8;
        *(float4*)op     = make_float4(oa[r][0]*inv, oa[r][1]*inv, oa[r][2]*inv, oa[r][3]*inv);
        *(float4*)(op+4) = make_float4(oa[r][4]*inv, oa[r][5]*inv, oa[r][6]*inv, oa[r][7]*inv);
    }
}

// ---------------- Launch ----------------
extern "C" void kernel_launch(void* const* d_in, const int* in_sizes, int n_in,
                              void* d_out, int out_size)
{
    const float* Xq  = (const float*)d_in[0];
    const float* Xkv = (const float*)d_in[1];
    const int*   qpos = (const int*)d_in[2];
    const int*   kpos = (const int*)d_in[3];
    const float* Wq  = (const float*)d_in[4];
    const float* Wk  = (const float*)d_in[5];
    const float* Wv  = (const float*)d_in[6];
    const float* Wo  = (const float*)d_in[7];
    float* out = (float*)d_out;

    float *qb, *kb, *vb, *ab;
    cudaGetSymbolAddress((void**)&qb, g_q);
    cudaGetSymbolAddress((void**)&kb, g_k);
    cudaGetSymbolAddress((void**)&vb, g_v);
    cudaGetSymbolAddress((void**)&ab, g_attn);

    dim3 blk(256);
    // Projections (flattened row-major GEMMs)
    sgemm128<<<dim3(16, 16), blk>>>(Xq,  Wq, qb, 2048, 2048, 2048);
    sgemm128<<<dim3(4,  16), blk>>>(Xkv, Wk, kb, 2048, 512,  2048);
    sgemm128<<<dim3(4,  16), blk>>>(Xkv, Wv, vb, 2048, 512,  2048);

    // RoPE on q and k
    rope_kernel<<<(B_*T_*NQ*64 + 255) / 256, 256>>>(qb, qpos, B_*T_*NQ*64, NQ);
    rope_kernel<<<(B_*S_*NKV*64 + 255) / 256, 256>>>(kb, kpos, B_*S_*NKV*64, NKV);

    // Attention
    const int ATTN_SMEM = (2 * 128 * PAD + 64 * 128 + 64 * PAD) * (int)sizeof(float); // 119808
    cudaFuncSetAttribute(attn_kernel, cudaFuncAttributeMaxDynamicSharedMemorySize, ATTN_SMEM);
    attn_kernel<<<dim3(T_/64, NQ, B_), blk, ATTN_SMEM>>>(qb, kb, vb, ab);

    // Output projection
    sgemm128<<<dim3(16, 16), blk>>>(ab, Wo, out, 2048, 2048, 2048);
}

// round 2
// speedup vs baseline: 1.5671x; 1.5671x over previous
#include <cuda_runtime.h>
#include <cstdint>

#define B_  2
#define T_  1024
#define S_  1024
#define NQ  16
#define NKV 4
#define HD  128

// Scratch (allocation-free rule: __device__ globals)
__device__ float g_q[B_*T_*NQ*HD];      // (B,T,NQ,HD)
__device__ float g_k[B_*S_*NKV*HD];     // (B,S,NKV,HD)
__device__ float g_v[B_*S_*NKV*HD];
__device__ float g_attn[B_*T_*NQ*HD];

// ---------------------------------------------------------------------------
// tf32 helpers
// ---------------------------------------------------------------------------
__device__ __forceinline__ float tf32_rna(float x) {
    float y;
    asm("cvt.rna.tf32.f32 %0, %1;" : "=f"(y) : "f"(x));
    return y;
}

__device__ __forceinline__ void mma_tf32(float d[4],
                                         uint32_t a0, uint32_t a1, uint32_t a2, uint32_t a3,
                                         uint32_t b0, uint32_t b1)
{
    asm volatile(
        "mma.sync.aligned.m16n8k8.row.col.f32.tf32.tf32.f32 "
        "{%0,%1,%2,%3}, {%4,%5,%6,%7}, {%8,%9}, {%0,%1,%2,%3};\n"
        : "+f"(d[0]), "+f"(d[1]), "+f"(d[2]), "+f"(d[3])
        : "r"(a0), "r"(a1), "r"(a2), "r"(a3), "r"(b0), "r"(b1));
}

// ---------------------------------------------------------------------------
// Tensor-core GEMM: C[M,N] = A[M,K] @ B[K,N], row-major.
// CTA tile 128x128, BK=32, 256 threads (8 warps: 2 (M) x 4 (N)), warp tile 64x32.
// THREE=1: 3xTF32 split (fp32-class accuracy). THREE=0: single tf32 pass.
// Requires M%128==0, N%128==0, K%32==0.
// ---------------------------------------------------------------------------
#define AP 36    // A smem row stride (floats):  (36*grp + qid) % 32 = 4*grp+qid -> conflict-free
#define BP 136   // B smem row stride (floats):  (136*qid + grp) % 32 = 8*qid+grp -> conflict-free

template<int THREE>
__global__ void __launch_bounds__(256) mma_gemm(
    const float* __restrict__ A, const float* __restrict__ Bm,
    float* __restrict__ C, int M, int N, int K)
{
    extern __shared__ float sm[];
    float* As_hi = sm;                          // [128][AP]
    float* Bs_hi = As_hi + 128 * AP;            // [32][BP]
    float* As_lo = Bs_hi + 32 * BP;             // (THREE only)
    float* Bs_lo = As_lo + 128 * AP;

    const int tid  = threadIdx.x;
    const int lane = tid & 31;
    const int warp = tid >> 5;
    const int grp  = lane >> 2;
    const int qid  = lane & 3;
    const int wm   = (warp >> 2) * 64;   // warp M offset (0 / 64)
    const int wn   = (warp & 3) * 32;    // warp N offset
    const int row0 = blockIdx.y * 128;
    const int col0 = blockIdx.x * 128;

    float acc[4][4][4];
    #pragma unroll
    for (int i = 0; i < 4; i++)
        #pragma unroll
        for (int j = 0; j < 4; j++)
            #pragma unroll
            for (int c = 0; c < 4; c++) acc[i][j][c] = 0.f;

    float4 aReg[4], bReg[4];

    // prefetch first tile into registers
    #pragma unroll
    for (int i = 0; i < 4; i++) {
        int idx = tid + i * 256;
        int ar = idx >> 3, ac = (idx & 7) << 2;          // A: 128 rows x 8 float4
        aReg[i] = *(const float4*)(A + (size_t)(row0 + ar) * K + ac);
        int bk = idx >> 5, bn = (idx & 31) << 2;         // B: 32 rows x 32 float4
        bReg[i] = *(const float4*)(Bm + (size_t)bk * N + col0 + bn);
    }

    for (int k0 = 0; k0 < K; k0 += 32) {
        // regs -> smem (with tf32 hi/lo split)
        #pragma unroll
        for (int i = 0; i < 4; i++) {
            int idx = tid + i * 256;
            int ar = idx >> 3, ac = (idx & 7) << 2;
            float4 v = aReg[i];
            float4 hi = make_float4(tf32_rna(v.x), tf32_rna(v.y), tf32_rna(v.z), tf32_rna(v.w));
            *(float4*)&As_hi[ar * AP + ac] = hi;
            if (THREE) {
                float4 lo = make_float4(v.x - hi.x, v.y - hi.y, v.z - hi.z, v.w - hi.w);
                *(float4*)&As_lo[ar * AP + ac] = lo;
            }
            int bk = idx >> 5, bn = (idx & 31) << 2;
            float4 w = bReg[i];
            float4 wh = make_float4(tf32_rna(w.x), tf32_rna(w.y), tf32_rna(w.z), tf32_rna(w.w));
            *(float4*)&Bs_hi[bk * BP + bn] = wh;
            if (THREE) {
                float4 wl = make_float4(w.x - wh.x, w.y - wh.y, w.z - wh.z, w.w - wh.w);
                *(float4*)&Bs_lo[bk * BP + bn] = wl;
            }
        }
        __syncthreads();

        // prefetch next tile
        if (k0 + 32 < K) {
            #pragma unroll
            for (int i = 0; i < 4; i++) {
                int idx = tid + i * 256;
                int ar = idx >> 3, ac = (idx & 7) << 2;
                aReg[i] = *(const float4*)(A + (size_t)(row0 + ar) * K + k0 + 32 + ac);
                int bk = idx >> 5, bn = (idx & 31) << 2;
                bReg[i] = *(const float4*)(Bm + (size_t)(k0 + 32 + bk) * N + col0 + bn);
            }
        }

        // compute: 4 k-steps of 8
        #pragma unroll
        for (int kk = 0; kk < 4; kk++) {
            const int kb = kk * 8;
            uint32_t a_hi[4][4], a_lo[4][4], b_hi[4][2], b_lo[4][2];
            #pragma unroll
            for (int im = 0; im < 4; im++) {
                int r = wm + im * 16 + grp;
                a_hi[im][0] = __float_as_uint(As_hi[r       * AP + kb + qid]);
                a_hi[im][1] = __float_as_uint(As_hi[(r + 8) * AP + kb + qid]);
                a_hi[im][2] = __float_as_uint(As_hi[r       * AP + kb + qid + 4]);
                a_hi[im][3] = __float_as_uint(As_hi[(r + 8) * AP + kb + qid + 4]);
                if (THREE) {
                    a_lo[im][0] = __float_as_uint(As_lo[r       * AP + kb + qid]);
                    a_lo[im][1] = __float_as_uint(As_lo[(r + 8) * AP + kb + qid]);
                    a_lo[im][2] = __float_as_uint(As_lo[r       * AP + kb + qid + 4]);
                    a_lo[im][3] = __float_as_uint(As_lo[(r + 8) * AP + kb + qid + 4]);
                }
            }
            #pragma unroll
            for (int in_ = 0; in_ < 4; in_++) {
                int nc = wn + in_ * 8 + grp;
                b_hi[in_][0] = __float_as_uint(Bs_hi[(kb + qid)     * BP + nc]);
                b_hi[in_][1] = __float_as_uint(Bs_hi[(kb + qid + 4) * BP + nc]);
                if (THREE) {
                    b_lo[in_][0] = __float_as_uint(Bs_lo[(kb + qid)     * BP + nc]);
                    b_lo[in_][1] = __float_as_uint(Bs_lo[(kb + qid + 4) * BP + nc]);
                }
            }
            #pragma unroll
            for (int im = 0; im < 4; im++)
                #pragma unroll
                for (int in_ = 0; in_ < 4; in_++) {
                    mma_tf32(acc[im][in_], a_hi[im][0], a_hi[im][1], a_hi[im][2], a_hi[im][3],
                             b_hi[in_][0], b_hi[in_][1]);
                    if (THREE) {
                        mma_tf32(acc[im][in_], a_hi[im][0], a_hi[im][1], a_hi[im][2], a_hi[im][3],
                                 b_lo[in_][0], b_lo[in_][1]);
                        mma_tf32(acc[im][in_], a_lo[im][0], a_lo[im][1], a_lo[im][2], a_lo[im][3],
                                 b_hi[in_][0], b_hi[in_][1]);
                    }
                }
        }
        __syncthreads();
    }

    // epilogue
    #pragma unroll
    for (int im = 0; im < 4; im++) {
        int r = row0 + wm + im * 16 + grp;
        #pragma unroll
        for (int in_ = 0; in_ < 4; in_++) {
            int nc = col0 + wn + in_ * 8 + 2 * qid;
            *(float2*)(C + (size_t)r * N + nc)       = make_float2(acc[im][in_][0], acc[im][in_][1]);
            *(float2*)(C + (size_t)(r + 8) * N + nc) = make_float2(acc[im][in_][2], acc[im][in_][3]);
        }
    }
}

// ---------------- RoPE (in-place): x (BL, Nh, HD), half = 64 ----------------
__global__ void rope_kernel(float* __restrict__ x, const int* __restrict__ pos,
                            int total, int Nh)
{
    int idx = blockIdx.x * blockDim.x + threadIdx.x;
    if (idx >= total) return;
    int i   = idx & 63;
    int bln = idx >> 6;
    int bl  = bln / Nh;
    float p    = (float)pos[bl];
    float frac = (float)i * (1.0f / 64.0f);
    float ts   = powf(10000.0f, frac);
    float ang  = p / ts;
    float si = sinf(ang), co = cosf(ang);
    float* base = x + (size_t)bln * HD;
    float x1 = base[i], x2 = base[i + 64];
    base[i]      = x1 * co - x2 * si;
    base[i + 64] = x2 * co + x1 * si;
}

// ---------------- Flash attention: per (b, head, 64-query tile) ----------------
#define PAD 68

__global__ void __launch_bounds__(256) attn_kernel(
    const float* __restrict__ q, const float* __restrict__ k,
    const float* __restrict__ v, float* __restrict__ o)
{
    extern __shared__ float smem[];
    float* Qt = smem;                 // [128][PAD]
    float* Kt = Qt + 128 * PAD;       // [128][PAD]
    float* Vs = Kt + 128 * PAD;       // [64][128]
    float* Ps = Vs + 64 * 128;        // [64][PAD]

    const int tid = threadIdx.x;
    const int tx = tid & 15, ty = tid >> 4;
    const int t0 = blockIdx.x * 64;
    const int n  = blockIdx.y;
    const int b  = blockIdx.z;
    const int kvh = n >> 2;

    const float* Qg = q + ((size_t)(b * T_ + t0) * NQ  + n)   * HD;
    const float* Kg = k + ((size_t)(b * S_)      * NKV + kvh) * HD;
    const float* Vg = v + ((size_t)(b * S_)      * NKV + kvh) * HD;

    for (int f = tid; f < 64 * 32; f += 256) {
        int r  = f >> 5;
        int h4 = (f & 31) << 2;
        float4 a = *(const float4*)(Qg + (size_t)r * (NQ * HD) + h4);
        Qt[(h4+0)*PAD + r] = a.x;
        Qt[(h4+1)*PAD + r] = a.y;
        Qt[(h4+2)*PAD + r] = a.z;
        Qt[(h4+3)*PAD + r] = a.w;
    }

    float m[4], l[4], oa[4][8];
    #pragma unroll
    for (int r = 0; r < 4; r++) {
        m[r] = -1e30f; l[r] = 0.f;
        #pragma unroll
        for (int c = 0; c < 8; c++) oa[r][c] = 0.f;
    }

    for (int s0 = 0; s0 < S_; s0 += 64) {
        __syncthreads();
        for (int f = tid; f < 64 * 32; f += 256) {
            int r  = f >> 5;
            int h4 = (f & 31) << 2;
            float4 a = *(const float4*)(Kg + (size_t)(s0 + r) * (NKV * HD) + h4);
            Kt[(h4+0)*PAD + r] = a.x;
            Kt[(h4+1)*PAD + r] = a.y;
            Kt[(h4+2)*PAD + r] = a.z;
            Kt[(h4+3)*PAD + r] = a.w;
            *(float4*)&Vs[r * 128 + h4] = *(const float4*)(Vg + (size_t)(s0 + r) * (NKV * HD) + h4);
        }
        __syncthreads();

        float s[4][4] = {};
        #pragma unroll 8
        for (int h = 0; h < 128; h++) {
            float qv[4], kv[4];
            *(float4*)qv = *(float4*)&Qt[h * PAD + ty * 4];
            *(float4*)kv = *(float4*)&Kt[h * PAD + tx * 4];
            #pragma unroll
            for (int r = 0; r < 4; r++)
                #pragma unroll
                for (int c = 0; c < 4; c++)
                    s[r][c] += qv[r] * kv[c];
        }

        #pragma unroll
        for (int r = 0; r < 4; r++) {
            float mx = fmaxf(fmaxf(s[r][0], s[r][1]), fmaxf(s[r][2], s[r][3]));
            #pragma unroll
            for (int off = 8; off; off >>= 1)
                mx = fmaxf(mx, __shfl_xor_sync(0xffffffffu, mx, off));
            float mnew = fmaxf(m[r], mx);
            float corr = __expf(m[r] - mnew);
            float psum = 0.f;
            #pragma unroll
            for (int c = 0; c < 4; c++) { s[r][c] = __expf(s[r][c] - mnew); psum += s[r][c]; }
            #pragma unroll
            for (int off = 8; off; off >>= 1)
                psum += __shfl_xor_sync(0xffffffffu, psum, off);
            l[r] = l[r] * corr + psum;
            m[r] = mnew;
            #pragma unroll
            for (int c = 0; c < 8; c++) oa[r][c] *= corr;
            *(float4*)&Ps[(ty*4 + r) * PAD + tx*4] = make_float4(s[r][0], s[r][1], s[r][2], s[r][3]);
        }
        __syncthreads();

        #pragma unroll 4
        for (int j = 0; j < 64; j++) {
            float pv[4], vv[8];
            #pragma unroll
            for (int r = 0; r < 4; r++) pv[r] = Ps[(ty*4 + r) * PAD + j];
            *(float4*)&vv[0] = *(float4*)&Vs[j * 128 + tx*8];
            *(float4*)&vv[4] = *(float4*)&Vs[j * 128 + tx*8 + 4];
            #pragma unroll
            for (int r = 0; r < 4; r++)
                #pragma unroll
                for (int c = 0; c < 8; c++)
                    oa[r][c] += pv[r] * vv[c];
        }
    }

    #pragma unroll
    for (int r = 0; r < 4; r++) {
        float inv = 1.0f / l[r];
        int t = t0 + ty*4 + r;
        float* op = o + ((size_t)(b * T_ + t) * NQ + n) * HD + tx*8;
        *(float4*)op     = make_float4(oa[r][0]*inv, oa[r][1]*inv, oa[r][2]*inv, oa[r][3]*inv);
        *(float4*)(op+4) = make_float4(oa[r][4]*inv, oa[r][5]*inv, oa[r][6]*inv, oa[r][7]*inv);
    }
}

// ---------------- Launch ----------------
extern "C" void kernel_launch(void* const* d_in, const int* in_sizes, int n_in,
                              void* d_out, int out_size)
{
    const float* Xq  = (const float*)d_in[0];
    const float* Xkv = (const float*)d_in[1];
    const int*   qpos = (const int*)d_in[2];
    const int*   kpos = (const int*)d_in[3];
    const float* Wq  = (const float*)d_in[4];
    const float* Wk  = (const float*)d_in[5];
    const float* Wv  = (const float*)d_in[6];
    const float* Wo  = (const float*)d_in[7];
    float* out = (float*)d_out;

    float *qb, *kb, *vb, *ab;
    cudaGetSymbolAddress((void**)&qb, g_q);
    cudaGetSymbolAddress((void**)&kb, g_k);
    cudaGetSymbolAddress((void**)&vb, g_v);
    cudaGetSymbolAddress((void**)&ab, g_attn);

    const int SM3X = (128 * AP * 2 + 32 * BP * 2) * (int)sizeof(float);  // 71680
    const int SM1X = (128 * AP + 32 * BP) * (int)sizeof(float);          // 35840
    static bool attr_done = false;
    if (!attr_done) {
        cudaFuncSetAttribute(mma_gemm<1>, cudaFuncAttributeMaxDynamicSharedMemorySize, SM3X);
        cudaFuncSetAttribute(mma_gemm<0>, cudaFuncAttributeMaxDynamicSharedMemorySize, SM1X);
        const int ATTN_SMEM = (2 * 128 * PAD + 64 * 128 + 64 * PAD) * (int)sizeof(float);
        cudaFuncSetAttribute(attn_kernel, cudaFuncAttributeMaxDynamicSharedMemorySize, ATTN_SMEM);
        attr_done = true;
    }

    dim3 blk(256);
    // Q and K projections: 3xTF32 (logit path needs fp32-class precision)
    mma_gemm<1><<<dim3(16, 16), blk, SM3X>>>(Xq,  Wq, qb, 2048, 2048, 2048);
    mma_gemm<1><<<dim3(4,  16), blk, SM3X>>>(Xkv, Wk, kb, 2048, 512,  2048);
    // V projection: single-pass tf32
    mma_gemm<0><<<dim3(4,  16), blk, SM1X>>>(Xkv, Wv, vb, 2048, 512,  2048);

    // RoPE on q and k
    rope_kernel<<<(B_*T_*NQ*64 + 255) / 256, 256>>>(qb, qpos, B_*T_*NQ*64, NQ);
    rope_kernel<<<(B_*S_*NKV*64 + 255) / 256, 256>>>(kb, kpos, B_*S_*NKV*64, NKV);

    // Attention (fp32 flash)
    const int ATTN_SMEM = (2 * 128 * PAD + 64 * 128 + 64 * PAD) * (int)sizeof(float);
    attn_kernel<<<dim3(T_/64, NQ, B_), blk, ATTN_SMEM>>>(qb, kb, vb, ab);

    // Output projection: single-pass tf32
    mma_gemm<0><<<dim3(16, 16), blk, SM1X>>>(ab, Wo, out, 2048, 2048, 2048);
}

// round 3
// speedup vs baseline: 2.2848x; 1.4580x over previous
#include <cuda_runtime.h>
#include <cstdint>

#define B_  2
#define T_  1024
#define S_  1024
#define NQ  16
#define NKV 4
#define HD  128

// Scratch (allocation-free rule: __device__ globals)
__device__ float g_q[B_*T_*NQ*HD];      // (B,T,NQ,HD)
__device__ float g_k[B_*S_*NKV*HD];     // (B,S,NKV,HD)
__device__ float g_v[B_*S_*NKV*HD];
__device__ float g_attn[B_*T_*NQ*HD];

// ---------------------------------------------------------------------------
// tf32 helpers
// ---------------------------------------------------------------------------
__device__ __forceinline__ float tf32_rna(float x) {
    float y;
    asm("cvt.rna.tf32.f32 %0, %1;" : "=f"(y) : "f"(x));
    return y;
}

__device__ __forceinline__ void mma_tf32(float d[4],
                                         uint32_t a0, uint32_t a1, uint32_t a2, uint32_t a3,
                                         uint32_t b0, uint32_t b1)
{
    asm volatile(
        "mma.sync.aligned.m16n8k8.row.col.f32.tf32.tf32.f32 "
        "{%0,%1,%2,%3}, {%4,%5,%6,%7}, {%8,%9}, {%0,%1,%2,%3};\n"
        : "+f"(d[0]), "+f"(d[1]), "+f"(d[2]), "+f"(d[3])
        : "r"(a0), "r"(a1), "r"(a2), "r"(a3), "r"(b0), "r"(b1));
}

// ---------------------------------------------------------------------------
// Tensor-core GEMM: C[M,N] = A[M,K] @ B[K,N], row-major (unchanged from R2).
// ---------------------------------------------------------------------------
#define AP 36
#define BP 136

template<int THREE>
__global__ void __launch_bounds__(256) mma_gemm(
    const float* __restrict__ A, const float* __restrict__ Bm,
    float* __restrict__ C, int M, int N, int K)
{
    extern __shared__ float sm[];
    float* As_hi = sm;
    float* Bs_hi = As_hi + 128 * AP;
    float* As_lo = Bs_hi + 32 * BP;
    float* Bs_lo = As_lo + 128 * AP;

    const int tid  = threadIdx.x;
    const int lane = tid & 31;
    const int warp = tid >> 5;
    const int grp  = lane >> 2;
    const int qid  = lane & 3;
    const int wm   = (warp >> 2) * 64;
    const int wn   = (warp & 3) * 32;
    const int row0 = blockIdx.y * 128;
    const int col0 = blockIdx.x * 128;

    float acc[4][4][4];
    #pragma unroll
    for (int i = 0; i < 4; i++)
        #pragma unroll
        for (int j = 0; j < 4; j++)
            #pragma unroll
            for (int c = 0; c < 4; c++) acc[i][j][c] = 0.f;

    float4 aReg[4], bReg[4];

    #pragma unroll
    for (int i = 0; i < 4; i++) {
        int idx = tid + i * 256;
        int ar = idx >> 3, ac = (idx & 7) << 2;
        aReg[i] = *(const float4*)(A + (size_t)(row0 + ar) * K + ac);
        int bk = idx >> 5, bn = (idx & 31) << 2;
        bReg[i] = *(const float4*)(Bm + (size_t)bk * N + col0 + bn);
    }

    for (int k0 = 0; k0 < K; k0 += 32) {
        #pragma unroll
        for (int i = 0; i < 4; i++) {
            int idx = tid + i * 256;
            int ar = idx >> 3, ac = (idx & 7) << 2;
            float4 v = aReg[i];
            float4 hi = make_float4(tf32_rna(v.x), tf32_rna(v.y), tf32_rna(v.z), tf32_rna(v.w));
            *(float4*)&As_hi[ar * AP + ac] = hi;
            if (THREE) {
                float4 lo = make_float4(v.x - hi.x, v.y - hi.y, v.z - hi.z, v.w - hi.w);
                *(float4*)&As_lo[ar * AP + ac] = lo;
            }
            int bk = idx >> 5, bn = (idx & 31) << 2;
            float4 w = bReg[i];
            float4 wh = make_float4(tf32_rna(w.x), tf32_rna(w.y), tf32_rna(w.z), tf32_rna(w.w));
            *(float4*)&Bs_hi[bk * BP + bn] = wh;
            if (THREE) {
                float4 wl = make_float4(w.x - wh.x, w.y - wh.y, w.z - wh.z, w.w - wh.w);
                *(float4*)&Bs_lo[bk * BP + bn] = wl;
            }
        }
        __syncthreads();

        if (k0 + 32 < K) {
            #pragma unroll
            for (int i = 0; i < 4; i++) {
                int idx = tid + i * 256;
                int ar = idx >> 3, ac = (idx & 7) << 2;
                aReg[i] = *(const float4*)(A + (size_t)(row0 + ar) * K + k0 + 32 + ac);
                int bk = idx >> 5, bn = (idx & 31) << 2;
                bReg[i] = *(const float4*)(Bm + (size_t)(k0 + 32 + bk) * N + col0 + bn);
            }
        }

        #pragma unroll
        for (int kk = 0; kk < 4; kk++) {
            const int kb = kk * 8;
            uint32_t a_hi[4][4], a_lo[4][4], b_hi[4][2], b_lo[4][2];
            #pragma unroll
            for (int im = 0; im < 4; im++) {
                int r = wm + im * 16 + grp;
                a_hi[im][0] = __float_as_uint(As_hi[r       * AP + kb + qid]);
                a_hi[im][1] = __float_as_uint(As_hi[(r + 8) * AP + kb + qid]);
                a_hi[im][2] = __float_as_uint(As_hi[r       * AP + kb + qid + 4]);
                a_hi[im][3] = __float_as_uint(As_hi[(r + 8) * AP + kb + qid + 4]);
                if (THREE) {
                    a_lo[im][0] = __float_as_uint(As_lo[r       * AP + kb + qid]);
                    a_lo[im][1] = __float_as_uint(As_lo[(r + 8) * AP + kb + qid]);
                    a_lo[im][2] = __float_as_uint(As_lo[r       * AP + kb + qid + 4]);
                    a_lo[im][3] = __float_as_uint(As_lo[(r + 8) * AP + kb + qid + 4]);
                }
            }
            #pragma unroll
            for (int in_ = 0; in_ < 4; in_++) {
                int nc = wn + in_ * 8 + grp;
                b_hi[in_][0] = __float_as_uint(Bs_hi[(kb + qid)     * BP + nc]);
                b_hi[in_][1] = __float_as_uint(Bs_hi[(kb + qid + 4) * BP + nc]);
                if (THREE) {
                    b_lo[in_][0] = __float_as_uint(Bs_lo[(kb + qid)     * BP + nc]);
                    b_lo[in_][1] = __float_as_uint(Bs_lo[(kb + qid + 4) * BP + nc]);
                }
            }
            #pragma unroll
            for (int im = 0; im < 4; im++)
                #pragma unroll
                for (int in_ = 0; in_ < 4; in_++) {
                    mma_tf32(acc[im][in_], a_hi[im][0], a_hi[im][1], a_hi[im][2], a_hi[im][3],
                             b_hi[in_][0], b_hi[in_][1]);
                    if (THREE) {
                        mma_tf32(acc[im][in_], a_hi[im][0], a_hi[im][1], a_hi[im][2], a_hi[im][3],
                                 b_lo[in_][0], b_lo[in_][1]);
                        mma_tf32(acc[im][in_], a_lo[im][0], a_lo[im][1], a_lo[im][2], a_lo[im][3],
                                 b_hi[in_][0], b_hi[in_][1]);
                    }
                }
        }
        __syncthreads();
    }

    #pragma unroll
    for (int im = 0; im < 4; im++) {
        int r = row0 + wm + im * 16 + grp;
        #pragma unroll
        for (int in_ = 0; in_ < 4; in_++) {
            int nc = col0 + wn + in_ * 8 + 2 * qid;
            *(float2*)(C + (size_t)r * N + nc)       = make_float2(acc[im][in_][0], acc[im][in_][1]);
            *(float2*)(C + (size_t)(r + 8) * N + nc) = make_float2(acc[im][in_][2], acc[im][in_][3]);
        }
    }
}

// ---------------- RoPE (in-place): x (BL, Nh, HD), half = 64 ----------------
__global__ void rope_kernel(float* __restrict__ x, const int* __restrict__ pos,
                            int total, int Nh)
{
    int idx = blockIdx.x * blockDim.x + threadIdx.x;
    if (idx >= total) return;
    int i   = idx & 63;
    int bln = idx >> 6;
    int bl  = bln / Nh;
    float p    = (float)pos[bl];
    float frac = (float)i * (1.0f / 64.0f);
    float ts   = powf(10000.0f, frac);
    float ang  = p / ts;
    float si = sinf(ang), co = cosf(ang);
    float* base = x + (size_t)bln * HD;
    float x1 = base[i], x2 = base[i + 64];
    base[i]      = x1 * co - x2 * si;
    base[i + 64] = x2 * co + x1 * si;
}

// ---------------------------------------------------------------------------
// Tensor-core flash attention. CTA = 128 queries x 1 head. 8 warps,
// warp w owns query rows [16w, 16w+16). QK^T: 3xTF32 split. PV: 1x tf32.
// Smem strides chosen for conflict-free MMA fragment gathers:
//   Q/K stride 132 -> bank (4*grp+qid); P stride 68 -> (4g+q); V stride 136 -> (8q+g).
// ---------------------------------------------------------------------------
#define QSS 132
#define KSS 132
#define VSS 136
#define PSS 68

__global__ void __launch_bounds__(256) attn_tc_kernel(
    const float* __restrict__ q, const float* __restrict__ k,
    const float* __restrict__ v, float* __restrict__ o)
{
    extern __shared__ float sm[];
    float* Qs = sm;                      // [128][132]
    float* Ks = Qs + 128 * QSS;          // [64][132]
    float* Vs = Ks + 64 * KSS;           // [64][136]
    float* Ps = Vs + 64 * VSS;           // [128][68]

    const int tid  = threadIdx.x;
    const int lane = tid & 31;
    const int warp = tid >> 5;
    const int grp  = lane >> 2;
    const int qid  = lane & 3;
    const int wm   = warp * 16;
    const int t0   = blockIdx.x * 128;
    const int n    = blockIdx.y;
    const int b    = blockIdx.z;
    const int kvh  = n >> 2;

    const float* Qg = q + ((size_t)(b * T_ + t0) * NQ  + n)   * HD;
    const float* Kg = k + ((size_t)(b * S_)      * NKV + kvh) * HD;
    const float* Vg = v + ((size_t)(b * S_)      * NKV + kvh) * HD;

    // Load Q tile [128][128]
    for (int f = tid; f < 128 * 32; f += 256) {
        int r = f >> 5, c4 = (f & 31) << 2;
        *(float4*)&Qs[r * QSS + c4] = *(const float4*)(Qg + (size_t)r * (NQ * HD) + c4);
    }

    float m0 = -1e30f, m1 = -1e30f, l0 = 0.f, l1 = 0.f;
    float oacc[16][4];
    #pragma unroll
    for (int j = 0; j < 16; j++)
        #pragma unroll
        for (int c = 0; c < 4; c++) oacc[j][c] = 0.f;

    const int rA0 = (wm + grp) * QSS;
    const int rA1 = (wm + grp + 8) * QSS;
    const int rP0 = (wm + grp) * PSS;
    const int rP1 = (wm + grp + 8) * PSS;

    for (int s0 = 0; s0 < S_; s0 += 64) {
        __syncthreads();   // prev iter done reading Ks/Vs
        for (int f = tid; f < 64 * 32; f += 256) {
            int r = f >> 5, c4 = (f & 31) << 2;
            *(float4*)&Ks[r * KSS + c4] = *(const float4*)(Kg + (size_t)(s0 + r) * (NKV * HD) + c4);
            *(float4*)&Vs[r * VSS + c4] = *(const float4*)(Vg + (size_t)(s0 + r) * (NKV * HD) + c4);
        }
        __syncthreads();

        // ---- S = Q K^T (3x tf32) ----
        float sacc[8][4];
        #pragma unroll
        for (int j = 0; j < 8; j++)
            #pragma unroll
            for (int c = 0; c < 4; c++) sacc[j][c] = 0.f;

        for (int kk = 0; kk < 16; kk++) {
            const int k0 = kk * 8;
            float a0f = Qs[rA0 + k0 + qid];
            float a1f = Qs[rA1 + k0 + qid];
            float a2f = Qs[rA0 + k0 + qid + 4];
            float a3f = Qs[rA1 + k0 + qid + 4];
            float a0h = tf32_rna(a0f), a1h = tf32_rna(a1f), a2h = tf32_rna(a2f), a3h = tf32_rna(a3f);
            uint32_t ah0 = __float_as_uint(a0h), ah1 = __float_as_uint(a1h);
            uint32_t ah2 = __float_as_uint(a2h), ah3 = __float_as_uint(a3h);
            uint32_t al0 = __float_as_uint(a0f - a0h), al1 = __float_as_uint(a1f - a1h);
            uint32_t al2 = __float_as_uint(a2f - a2h), al3 = __float_as_uint(a3f - a3h);
            #pragma unroll
            for (int j = 0; j < 8; j++) {
                const int kr = (j * 8 + grp) * KSS + k0;
                float b0f = Ks[kr + qid];
                float b1f = Ks[kr + qid + 4];
                float b0h = tf32_rna(b0f), b1h = tf32_rna(b1f);
                uint32_t bh0 = __float_as_uint(b0h), bh1 = __float_as_uint(b1h);
                uint32_t bl0 = __float_as_uint(b0f - b0h), bl1 = __float_as_uint(b1f - b1h);
                mma_tf32(sacc[j], ah0, ah1, ah2, ah3, bh0, bh1);
                mma_tf32(sacc[j], ah0, ah1, ah2, ah3, bl0, bl1);
                mma_tf32(sacc[j], al0, al1, al2, al3, bh0, bh1);
            }
        }

        // ---- online softmax (rows grp / grp+8, quad-wide) ----
        float mx0 = -1e30f, mx1 = -1e30f;
        #pragma unroll
        for (int j = 0; j < 8; j++) {
            mx0 = fmaxf(mx0, fmaxf(sacc[j][0], sacc[j][1]));
            mx1 = fmaxf(mx1, fmaxf(sacc[j][2], sacc[j][3]));
        }
        #pragma unroll
        for (int off = 1; off < 4; off <<= 1) {
            mx0 = fmaxf(mx0, __shfl_xor_sync(0xffffffffu, mx0, off));
            mx1 = fmaxf(mx1, __shfl_xor_sync(0xffffffffu, mx1, off));
        }
        float mn0 = fmaxf(m0, mx0), mn1 = fmaxf(m1, mx1);
        float cr0 = __expf(m0 - mn0), cr1 = __expf(m1 - mn1);
        float ps0 = 0.f, ps1 = 0.f;
        #pragma unroll
        for (int j = 0; j < 8; j++) {
            float e0 = __expf(sacc[j][0] - mn0);
            float e1 = __expf(sacc[j][1] - mn0);
            float e2 = __expf(sacc[j][2] - mn1);
            float e3 = __expf(sacc[j][3] - mn1);
            ps0 += e0 + e1; ps1 += e2 + e3;
            *(float2*)&Ps[rP0 + j * 8 + 2 * qid] = make_float2(e0, e1);
            *(float2*)&Ps[rP1 + j * 8 + 2 * qid] = make_float2(e2, e3);
        }
        #pragma unroll
        for (int off = 1; off < 4; off <<= 1) {
            ps0 += __shfl_xor_sync(0xffffffffu, ps0, off);
            ps1 += __shfl_xor_sync(0xffffffffu, ps1, off);
        }
        l0 = l0 * cr0 + ps0; m0 = mn0;
        l1 = l1 * cr1 + ps1; m1 = mn1;
        #pragma unroll
        for (int j = 0; j < 16; j++) {
            oacc[j][0] *= cr0; oacc[j][1] *= cr0;
            oacc[j][2] *= cr1; oacc[j][3] *= cr1;
        }

        // ---- O += P V (1x tf32). P rows are warp-private: no barrier needed. ----
        for (int kk = 0; kk < 8; kk++) {
            const int k0 = kk * 8;
            uint32_t pa0 = __float_as_uint(tf32_rna(Ps[rP0 + k0 + qid]));
            uint32_t pa1 = __float_as_uint(tf32_rna(Ps[rP1 + k0 + qid]));
            uint32_t pa2 = __float_as_uint(tf32_rna(Ps[rP0 + k0 + qid + 4]));
            uint32_t pa3 = __float_as_uint(tf32_rna(Ps[rP1 + k0 + qid + 4]));
            const int vr0 = (k0 + qid) * VSS + grp;
            const int vr1 = (k0 + qid + 4) * VSS + grp;
            #pragma unroll
            for (int j = 0; j < 16; j++) {
                uint32_t vb0 = __float_as_uint(tf32_rna(Vs[vr0 + j * 8]));
                uint32_t vb1 = __float_as_uint(tf32_rna(Vs[vr1 + j * 8]));
                mma_tf32(oacc[j], pa0, pa1, pa2, pa3, vb0, vb1);
            }
        }
    }

    // ---- epilogue ----
    float inv0 = 1.0f / l0, inv1 = 1.0f / l1;
    float* o0 = o + ((size_t)(b * T_ + t0 + wm + grp)     * NQ + n) * HD;
    float* o1 = o + ((size_t)(b * T_ + t0 + wm + grp + 8) * NQ + n) * HD;
    #pragma unroll
    for (int j = 0; j < 16; j++) {
        int col = j * 8 + 2 * qid;
        *(float2*)(o0 + col) = make_float2(oacc[j][0] * inv0, oacc[j][1] * inv0);
        *(float2*)(o1 + col) = make_float2(oacc[j][2] * inv1, oacc[j][3] * inv1);
    }
}

// ---------------- Launch ----------------
extern "C" void kernel_launch(void* const* d_in, const int* in_sizes, int n_in,
                              void* d_out, int out_size)
{
    const float* Xq  = (const float*)d_in[0];
    const float* Xkv = (const float*)d_in[1];
    const int*   qpos = (const int*)d_in[2];
    const int*   kpos = (const int*)d_in[3];
    const float* Wq  = (const float*)d_in[4];
    const float* Wk  = (const float*)d_in[5];
    const float* Wv  = (const float*)d_in[6];
    const float* Wo  = (const float*)d_in[7];
    float* out = (float*)d_out;

    float *qb, *kb, *vb, *ab;
    cudaGetSymbolAddress((void**)&qb, g_q);
    cudaGetSymbolAddress((void**)&kb, g_k);
    cudaGetSymbolAddress((void**)&vb, g_v);
    cudaGetSymbolAddress((void**)&ab, g_attn);

    const int SM3X = (128 * AP * 2 + 32 * BP * 2) * (int)sizeof(float);  // 71680
    const int SM1X = (128 * AP + 32 * BP) * (int)sizeof(float);          // 35840
    const int ATTN_SMEM = (128 * QSS + 64 * KSS + 64 * VSS + 128 * PSS) * (int)sizeof(float); // 171008
    cudaFuncSetAttribute(mma_gemm<1>, cudaFuncAttributeMaxDynamicSharedMemorySize, SM3X);
    cudaFuncSetAttribute(mma_gemm<0>, cudaFuncAttributeMaxDynamicSharedMemorySize, SM1X);
    cudaFuncSetAttribute(attn_tc_kernel, cudaFuncAttributeMaxDynamicSharedMemorySize, ATTN_SMEM);

    dim3 blk(256);
    // Q and K projections: 3xTF32 (logit path needs fp32-class precision)
    mma_gemm<1><<<dim3(16, 16), blk, SM3X>>>(Xq,  Wq, qb, 2048, 2048, 2048);
    mma_gemm<1><<<dim3(4,  16), blk, SM3X>>>(Xkv, Wk, kb, 2048, 512,  2048);
    // V projection: single-pass tf32
    mma_gemm<0><<<dim3(4,  16), blk, SM1X>>>(Xkv, Wv, vb, 2048, 512,  2048);

    // RoPE on q and k
    rope_kernel<<<(B_*T_*NQ*64 + 255) / 256, 256>>>(qb, qpos, B_*T_*NQ*64, NQ);
    rope_kernel<<<(B_*S_*NKV*64 + 255) / 256, 256>>>(kb, kpos, B_*S_*NKV*64, NKV);

    // Attention (tensor-core flash)
    attn_tc_kernel<<<dim3(T_/128, NQ, B_), blk, ATTN_SMEM>>>(qb, kb, vb, ab);

    // Output projection: single-pass tf32
    mma_gemm<0><<<dim3(16, 16), blk, SM1X>>>(ab, Wo, out, 2048, 2048, 2048);
}

// round 4
// speedup vs baseline: 2.9353x; 1.2847x over previous
#include <cuda_runtime.h>
#include <cuda_bf16.h>
#include <cstdint>

#define B_  2
#define T_  1024
#define S_  1024
#define NQ  16
#define NKV 4
#define HD  128

// Scratch (allocation-free rule: __device__ globals)
__device__ float g_q[B_*T_*NQ*HD];      // (B,T,NQ,HD)
__device__ float g_k[B_*S_*NKV*HD];     // (B,S,NKV,HD)
__device__ float g_v[B_*S_*NKV*HD];
__device__ float g_attn[B_*T_*NQ*HD];

// ---------------------------------------------------------------------------
// helpers
// ---------------------------------------------------------------------------
__device__ __forceinline__ float tf32_rna(float x) {
    float y;
    asm("cvt.rna.tf32.f32 %0, %1;" : "=f"(y) : "f"(x));
    return y;
}

__device__ __forceinline__ void mma_tf32(float d[4],
                                         uint32_t a0, uint32_t a1, uint32_t a2, uint32_t a3,
                                         uint32_t b0, uint32_t b1)
{
    asm volatile(
        "mma.sync.aligned.m16n8k8.row.col.f32.tf32.tf32.f32 "
        "{%0,%1,%2,%3}, {%4,%5,%6,%7}, {%8,%9}, {%0,%1,%2,%3};\n"
        : "+f"(d[0]), "+f"(d[1]), "+f"(d[2]), "+f"(d[3])
        : "r"(a0), "r"(a1), "r"(a2), "r"(a3), "r"(b0), "r"(b1));
}

__device__ __forceinline__ void mma_bf16(float d[4], const uint32_t a[4], const uint32_t b[2])
{
    asm volatile(
        "mma.sync.aligned.m16n8k16.row.col.f32.bf16.bf16.f32 "
        "{%0,%1,%2,%3}, {%4,%5,%6,%7}, {%8,%9}, {%0,%1,%2,%3};\n"
        : "+f"(d[0]), "+f"(d[1]), "+f"(d[2]), "+f"(d[3])
        : "r"(a[0]), "r"(a[1]), "r"(a[2]), "r"(a[3]), "r"(b[0]), "r"(b[1]));
}

__device__ __forceinline__ void ldsm_x4(uint32_t r[4], uint32_t addr) {
    asm volatile("ldmatrix.sync.aligned.m8n8.x4.shared.b16 {%0,%1,%2,%3}, [%4];"
                 : "=r"(r[0]), "=r"(r[1]), "=r"(r[2]), "=r"(r[3]) : "r"(addr));
}
__device__ __forceinline__ void ldsm_x2(uint32_t r[2], uint32_t addr) {
    asm volatile("ldmatrix.sync.aligned.m8n8.x2.shared.b16 {%0,%1}, [%2];"
                 : "=r"(r[0]), "=r"(r[1]) : "r"(addr));
}
__device__ __forceinline__ void ldsm_x2t(uint32_t r[2], uint32_t addr) {
    asm volatile("ldmatrix.sync.aligned.m8n8.x2.trans.shared.b16 {%0,%1}, [%2];"
                 : "=r"(r[0]), "=r"(r[1]) : "r"(addr));
}

// split two floats into packed bf16 hi / lo pairs
__device__ __forceinline__ void bf16_split2(float x, float y, uint32_t& hi, uint32_t& lo) {
    __nv_bfloat16 hx = __float2bfloat16(x);
    __nv_bfloat16 hy = __float2bfloat16(y);
    __nv_bfloat16 lx = __float2bfloat16(x - __bfloat162float(hx));
    __nv_bfloat16 ly = __float2bfloat16(y - __bfloat162float(hy));
    hi = (uint32_t)__bfloat16_as_ushort(hx) | ((uint32_t)__bfloat16_as_ushort(hy) << 16);
    lo = (uint32_t)__bfloat16_as_ushort(lx) | ((uint32_t)__bfloat16_as_ushort(ly) << 16);
}

// ---------------------------------------------------------------------------
// bf16 3-pass GEMM (fp32-class accuracy): C[M,N] = A[M,K] @ B[K,N], row-major.
// CTA 128x128, BK=32, 256 threads (8 warps 2x4), warp tile 64x32.
// Smem (bf16): Ah/Al [128][40], Bh/Bl [32][136]. LDSM-friendly strides
// (80B = 16*5, 272B = 16*17 -> 8-row phases hit distinct 16B banks).
// ---------------------------------------------------------------------------
#define G_AH 0
#define G_AL 10240
#define G_BH 20480
#define G_BL 29184
#define G_SMEM 37888

__global__ void __launch_bounds__(256) gemm_bf3(
    const float* __restrict__ A, const float* __restrict__ Bm,
    float* __restrict__ C, int M, int N, int K)
{
    extern __shared__ char smraw[];
    const uint32_t sb = (uint32_t)__cvta_generic_to_shared(smraw);

    const int tid  = threadIdx.x;
    const int lane = tid & 31;
    const int warp = tid >> 5;
    const int grp  = lane >> 2;
    const int qid  = lane & 3;
    const int wm   = (warp >> 2) * 64;
    const int wn   = (warp & 3) * 32;
    const int row0 = blockIdx.y * 128;
    const int col0 = blockIdx.x * 128;

    float acc[4][4][4];
    #pragma unroll
    for (int i = 0; i < 4; i++)
        #pragma unroll
        for (int j = 0; j < 4; j++)
            #pragma unroll
            for (int c = 0; c < 4; c++) acc[i][j][c] = 0.f;

    float4 aReg[4], bReg[4];
    #pragma unroll
    for (int i = 0; i < 4; i++) {
        int idx = tid + i * 256;
        int ar = idx >> 3, ac = (idx & 7) << 2;
        aReg[i] = *(const float4*)(A + (size_t)(row0 + ar) * K + ac);
        int bk = idx >> 5, bn = (idx & 31) << 2;
        bReg[i] = *(const float4*)(Bm + (size_t)bk * N + col0 + bn);
    }

    for (int k0 = 0; k0 < K; k0 += 32) {
        #pragma unroll
        for (int i = 0; i < 4; i++) {
            int idx = tid + i * 256;
            int ar = idx >> 3, ac = (idx & 7) << 2;
            uint32_t h01, l01, h23, l23;
            bf16_split2(aReg[i].x, aReg[i].y, h01, l01);
            bf16_split2(aReg[i].z, aReg[i].w, h23, l23);
            int aoff = (ar * 40 + ac) << 1;
            *(uint2*)(smraw + G_AH + aoff) = make_uint2(h01, h23);
            *(uint2*)(smraw + G_AL + aoff) = make_uint2(l01, l23);

            int bk = idx >> 5, bn = (idx & 31) << 2;
            bf16_split2(bReg[i].x, bReg[i].y, h01, l01);
            bf16_split2(bReg[i].z, bReg[i].w, h23, l23);
            int boff = (bk * 136 + bn) << 1;
            *(uint2*)(smraw + G_BH + boff) = make_uint2(h01, h23);
            *(uint2*)(smraw + G_BL + boff) = make_uint2(l01, l23);
        }
        __syncthreads();

        if (k0 + 32 < K) {
            #pragma unroll
            for (int i = 0; i < 4; i++) {
                int idx = tid + i * 256;
                int ar = idx >> 3, ac = (idx & 7) << 2;
                aReg[i] = *(const float4*)(A + (size_t)(row0 + ar) * K + k0 + 32 + ac);
                int bk = idx >> 5, bn = (idx & 31) << 2;
                bReg[i] = *(const float4*)(Bm + (size_t)(k0 + 32 + bk) * N + col0 + bn);
            }
        }

        #pragma unroll
        for (int kk = 0; kk < 32; kk += 16) {
            uint32_t ah[4][4], al[4][4];
            #pragma unroll
            for (int im = 0; im < 4; im++) {
                int m = wm + im * 16 + (lane & 15);
                uint32_t ab = sb + G_AH + ((m * 40 + kk + ((lane >> 4) << 3)) << 1);
                ldsm_x4(ah[im], ab);
                ldsm_x4(al[im], ab + (G_AL - G_AH));
            }
            uint32_t bh[4][2], bl[4][2];
            #pragma unroll
            for (int in_ = 0; in_ < 4; in_++) {
                int kr = kk + (lane & 15);
                uint32_t bb = sb + G_BH + ((kr * 136 + wn + in_ * 8) << 1);
                ldsm_x2t(bh[in_], bb);
                ldsm_x2t(bl[in_], bb + (G_BL - G_BH));
            }
            #pragma unroll
            for (int im = 0; im < 4; im++)
                #pragma unroll
                for (int in_ = 0; in_ < 4; in_++) {
                    mma_bf16(acc[im][in_], ah[im], bh[in_]);
                    mma_bf16(acc[im][in_], ah[im], bl[in_]);
                    mma_bf16(acc[im][in_], al[im], bh[in_]);
                }
        }
        __syncthreads();
    }

    #pragma unroll
    for (int im = 0; im < 4; im++) {
        int r = row0 + wm + im * 16 + grp;
        #pragma unroll
        for (int in_ = 0; in_ < 4; in_++) {
            int nc = col0 + wn + in_ * 8 + 2 * qid;
            *(float2*)(C + (size_t)r * N + nc)       = make_float2(acc[im][in_][0], acc[im][in_][1]);
            *(float2*)(C + (size_t)(r + 8) * N + nc) = make_float2(acc[im][in_][2], acc[im][in_][3]);
        }
    }
}

// ---------------------------------------------------------------------------
// 1x tf32 GEMM (for V and output projections) — unchanged from R3.
// ---------------------------------------------------------------------------
#define AP 36
#define BP 136

__global__ void __launch_bounds__(256) mma_gemm1(
    const float* __restrict__ A, const float* __restrict__ Bm,
    float* __restrict__ C, int M, int N, int K)
{
    extern __shared__ float sm[];
    float* As_hi = sm;
    float* Bs_hi = As_hi + 128 * AP;

    const int tid  = threadIdx.x;
    const int lane = tid & 31;
    const int warp = tid >> 5;
    const int grp  = lane >> 2;
    const int qid  = lane & 3;
    const int wm   = (warp >> 2) * 64;
    const int wn   = (warp & 3) * 32;
    const int row0 = blockIdx.y * 128;
    const int col0 = blockIdx.x * 128;

    float acc[4][4][4];
    #pragma unroll
    for (int i = 0; i < 4; i++)
        #pragma unroll
        for (int j = 0; j < 4; j++)
            #pragma unroll
            for (int c = 0; c < 4; c++) acc[i][j][c] = 0.f;

    float4 aReg[4], bReg[4];
    #pragma unroll
    for (int i = 0; i < 4; i++) {
        int idx = tid + i * 256;
        int ar = idx >> 3, ac = (idx & 7) << 2;
        aReg[i] = *(const float4*)(A + (size_t)(row0 + ar) * K + ac);
        int bk = idx >> 5, bn = (idx & 31) << 2;
        bReg[i] = *(const float4*)(Bm + (size_t)bk * N + col0 + bn);
    }

    for (int k0 = 0; k0 < K; k0 += 32) {
        #pragma unroll
        for (int i = 0; i < 4; i++) {
            int idx = tid + i * 256;
            int ar = idx >> 3, ac = (idx & 7) << 2;
            float4 v = aReg[i];
            float4 hi = make_float4(tf32_rna(v.x), tf32_rna(v.y), tf32_rna(v.z), tf32_rna(v.w));
            *(float4*)&As_hi[ar * AP + ac] = hi;
            int bk = idx >> 5, bn = (idx & 31) << 2;
            float4 w = bReg[i];
            float4 wh = make_float4(tf32_rna(w.x), tf32_rna(w.y), tf32_rna(w.z), tf32_rna(w.w));
            *(float4*)&Bs_hi[bk * BP + bn] = wh;
        }
        __syncthreads();

        if (k0 + 32 < K) {
            #pragma unroll
            for (int i = 0; i < 4; i++) {
                int idx = tid + i * 256;
                int ar = idx >> 3, ac = (idx & 7) << 2;
                aReg[i] = *(const float4*)(A + (size_t)(row0 + ar) * K + k0 + 32 + ac);
                int bk = idx >> 5, bn = (idx & 31) << 2;
                bReg[i] = *(const float4*)(Bm + (size_t)(k0 + 32 + bk) * N + col0 + bn);
            }
        }

        #pragma unroll
        for (int kk = 0; kk < 4; kk++) {
            const int kb = kk * 8;
            uint32_t a_hi[4][4], b_hi[4][2];
            #pragma unroll
            for (int im = 0; im < 4; im++) {
                int r = wm + im * 16 + grp;
                a_hi[im][0] = __float_as_uint(As_hi[r       * AP + kb + qid]);
                a_hi[im][1] = __float_as_uint(As_hi[(r + 8) * AP + kb + qid]);
                a_hi[im][2] = __float_as_uint(As_hi[r       * AP + kb + qid + 4]);
                a_hi[im][3] = __float_as_uint(As_hi[(r + 8) * AP + kb + qid + 4]);
            }
            #pragma unroll
            for (int in_ = 0; in_ < 4; in_++) {
                int nc = wn + in_ * 8 + grp;
                b_hi[in_][0] = __float_as_uint(Bs_hi[(kb + qid)     * BP + nc]);
                b_hi[in_][1] = __float_as_uint(Bs_hi[(kb + qid + 4) * BP + nc]);
            }
            #pragma unroll
            for (int im = 0; im < 4; im++)
                #pragma unroll
                for (int in_ = 0; in_ < 4; in_++)
                    mma_tf32(acc[im][in_], a_hi[im][0], a_hi[im][1], a_hi[im][2], a_hi[im][3],
                             b_hi[in_][0], b_hi[in_][1]);
        }
        __syncthreads();
    }

    #pragma unroll
    for (int im = 0; im < 4; im++) {
        int r = row0 + wm + im * 16 + grp;
        #pragma unroll
        for (int in_ = 0; in_ < 4; in_++) {
            int nc = col0 + wn + in_ * 8 + 2 * qid;
            *(float2*)(C + (size_t)r * N + nc)       = make_float2(acc[im][in_][0], acc[im][in_][1]);
            *(float2*)(C + (size_t)(r + 8) * N + nc) = make_float2(acc[im][in_][2], acc[im][in_][3]);
        }
    }
}

// ---------------- RoPE (in-place): x (BL, Nh, HD), half = 64 ----------------
__global__ void rope_kernel(float* __restrict__ x, const int* __restrict__ pos,
                            int total, int Nh)
{
    int idx = blockIdx.x * blockDim.x + threadIdx.x;
    if (idx >= total) return;
    int i   = idx & 63;
    int bln = idx >> 6;
    int bl  = bln / Nh;
    float p    = (float)pos[bl];
    float frac = (float)i * (1.0f / 64.0f);
    float ts   = powf(10000.0f, frac);
    float ang  = p / ts;
    float si = sinf(ang), co = cosf(ang);
    float* base = x + (size_t)bln * HD;
    float x1 = base[i], x2 = base[i + 64];
    base[i]      = x1 * co - x2 * si;
    base[i + 64] = x2 * co + x1 * si;
}

// ---------------------------------------------------------------------------
// Tensor-core flash attention. CTA = 128 queries x 1 head, 8 warps,
// warp w owns rows [16w,16w+16). QK^T: 3-pass bf16 (LDSM). PV: 1x tf32.
// Smem (bytes): Qh 0, Ql 34816, Kh 69632, Kl 87040, Vs 104448 (fp32,[64][136]),
// Ps 139264 (fp32,[128][68]); total 174080.
// ---------------------------------------------------------------------------
#define A_QH 0
#define A_QL 34816
#define A_KH 69632
#define A_KL 87040
#define A_VS 104448
#define A_PS 139264
#define A_SMEM 174080
#define VSS 136
#define PSS 68

__global__ void __launch_bounds__(256) attn_tc_kernel(
    const float* __restrict__ q, const float* __restrict__ k,
    const float* __restrict__ v, float* __restrict__ o)
{
    extern __shared__ char smraw[];
    const uint32_t sb = (uint32_t)__cvta_generic_to_shared(smraw);
    float* Vs = (float*)(smraw + A_VS);
    float* Ps = (float*)(smraw + A_PS);

    const int tid  = threadIdx.x;
    const int lane = tid & 31;
    const int warp = tid >> 5;
    const int grp  = lane >> 2;
    const int qid  = lane & 3;
    const int wm   = warp * 16;
    const int t0   = blockIdx.x * 128;
    const int n    = blockIdx.y;
    const int b    = blockIdx.z;
    const int kvh  = n >> 2;

    const float* Qg = q + ((size_t)(b * T_ + t0) * NQ  + n)   * HD;
    const float* Kg = k + ((size_t)(b * S_)      * NKV + kvh) * HD;
    const float* Vg = v + ((size_t)(b * S_)      * NKV + kvh) * HD;

    // Load + split Q tile [128][128] -> bf16 hi/lo, stride 136
    for (int f = tid; f < 128 * 32; f += 256) {
        int r = f >> 5, c4 = (f & 31) << 2;
        float4 a = *(const float4*)(Qg + (size_t)r * (NQ * HD) + c4);
        uint32_t h01, l01, h23, l23;
        bf16_split2(a.x, a.y, h01, l01);
        bf16_split2(a.z, a.w, h23, l23);
        int off = (r * 136 + c4) << 1;
        *(uint2*)(smraw + A_QH + off) = make_uint2(h01, h23);
        *(uint2*)(smraw + A_QL + off) = make_uint2(l01, l23);
    }

    float m0 = -1e30f, m1 = -1e30f, l0 = 0.f, l1 = 0.f;
    float oacc[16][4];
    #pragma unroll
    for (int j = 0; j < 16; j++)
        #pragma unroll
        for (int c = 0; c < 4; c++) oacc[j][c] = 0.f;

    const int rP0 = (wm + grp) * PSS;
    const int rP1 = (wm + grp + 8) * PSS;

    for (int s0 = 0; s0 < S_; s0 += 64) {
        __syncthreads();   // prev iter done reading K/V/P (also orders Q on iter 0)
        for (int f = tid; f < 64 * 32; f += 256) {
            int r = f >> 5, c4 = (f & 31) << 2;
            float4 a = *(const float4*)(Kg + (size_t)(s0 + r) * (NKV * HD) + c4);
            uint32_t h01, l01, h23, l23;
            bf16_split2(a.x, a.y, h01, l01);
            bf16_split2(a.z, a.w, h23, l23);
            int off = (r * 136 + c4) << 1;
            *(uint2*)(smraw + A_KH + off) = make_uint2(h01, h23);
            *(uint2*)(smraw + A_KL + off) = make_uint2(l01, l23);
            *(float4*)&Vs[r * VSS + c4] = *(const float4*)(Vg + (size_t)(s0 + r) * (NKV * HD) + c4);
        }
        __syncthreads();

        // ---- S = Q K^T (3-pass bf16) ----
        float sacc[8][4];
        #pragma unroll
        for (int j = 0; j < 8; j++)
            #pragma unroll
            for (int c = 0; c < 4; c++) sacc[j][c] = 0.f;

        #pragma unroll
        for (int kk = 0; kk < 8; kk++) {
            const int col0h = kk * 16;
            uint32_t ah[4], al[4];
            {
                int m = wm + (lane & 15);
                uint32_t ab = sb + A_QH + ((m * 136 + col0h + ((lane >> 4) << 3)) << 1);
                ldsm_x4(ah, ab);
                ldsm_x4(al, ab + (A_QL - A_QH));
            }
            #pragma unroll
            for (int j = 0; j < 8; j++) {
                int row = j * 8 + (lane & 7);
                uint32_t bb = sb + A_KH + ((row * 136 + col0h + (lane & 8)) << 1);
                uint32_t bh[2], bl[2];
                ldsm_x2(bh, bb);
                ldsm_x2(bl, bb + (A_KL - A_KH));
                mma_bf16(sacc[j], ah, bh);
                mma_bf16(sacc[j], ah, bl);
                mma_bf16(sacc[j], al, bh);
            }
        }

        // ---- online softmax (rows grp / grp+8, quad-wide) ----
        float mx0 = -1e30f, mx1 = -1e30f;
        #pragma unroll
        for (int j = 0; j < 8; j++) {
            mx0 = fmaxf(mx0, fmaxf(sacc[j][0], sacc[j][1]));
            mx1 = fmaxf(mx1, fmaxf(sacc[j][2], sacc[j][3]));
        }
        #pragma unroll
        for (int off = 1; off < 4; off <<= 1) {
            mx0 = fmaxf(mx0, __shfl_xor_sync(0xffffffffu, mx0, off));
            mx1 = fmaxf(mx1, __shfl_xor_sync(0xffffffffu, mx1, off));
        }
        float mn0 = fmaxf(m0, mx0), mn1 = fmaxf(m1, mx1);
        float cr0 = __expf(m0 - mn0), cr1 = __expf(m1 - mn1);
        float ps0 = 0.f, ps1 = 0.f;
        #pragma unroll
        for (int j = 0; j < 8; j++) {
            float e0 = __expf(sacc[j][0] - mn0);
            float e1 = __expf(sacc[j][1] - mn0);
            float e2 = __expf(sacc[j][2] - mn1);
            float e3 = __expf(sacc[j][3] - mn1);
            ps0 += e0 + e1; ps1 += e2 + e3;
            *(float2*)&Ps[rP0 + j * 8 + 2 * qid] = make_float2(e0, e1);
            *(float2*)&Ps[rP1 + j * 8 + 2 * qid] = make_float2(e2, e3);
        }
        #pragma unroll
        for (int off = 1; off < 4; off <<= 1) {
            ps0 += __shfl_xor_sync(0xffffffffu, ps0, off);
            ps1 += __shfl_xor_sync(0xffffffffu, ps1, off);
        }
        l0 = l0 * cr0 + ps0; m0 = mn0;
        l1 = l1 * cr1 + ps1; m1 = mn1;
        #pragma unroll
        for (int j = 0; j < 16; j++) {
            oacc[j][0] *= cr0; oacc[j][1] *= cr0;
            oacc[j][2] *= cr1; oacc[j][3] *= cr1;
        }

        // ---- O += P V (1x tf32). P rows warp-private: no barrier needed. ----
        #pragma unroll
        for (int kk = 0; kk < 8; kk++) {
            const int k0 = kk * 8;
            uint32_t pa0 = __float_as_uint(tf32_rna(Ps[rP0 + k0 + qid]));
            uint32_t pa1 = __float_as_uint(tf32_rna(Ps[rP1 + k0 + qid]));
            uint32_t pa2 = __float_as_uint(tf32_rna(Ps[rP0 + k0 + qid + 4]));
            uint32_t pa3 = __float_as_uint(tf32_rna(Ps[rP1 + k0 + qid + 4]));
            const int vr0 = (k0 + qid) * VSS + grp;
            const int vr1 = (k0 + qid + 4) * VSS + grp;
            #pragma unroll
            for (int j = 0; j < 16; j++) {
                uint32_t vb0 = __float_as_uint(tf32_rna(Vs[vr0 + j * 8]));
                uint32_t vb1 = __float_as_uint(tf32_rna(Vs[vr1 + j * 8]));
                mma_tf32(oacc[j], pa0, pa1, pa2, pa3, vb0, vb1);
            }
        }
    }

    // ---- epilogue ----
    float inv0 = 1.0f / l0, inv1 = 1.0f / l1;
    float* o0 = o + ((size_t)(b * T_ + t0 + wm + grp)     * NQ + n) * HD;
    float* o1 = o + ((size_t)(b * T_ + t0 + wm + grp + 8) * NQ + n) * HD;
    #pragma unroll
    for (int j = 0; j < 16; j++) {
        int col = j * 8 + 2 * qid;
        *(float2*)(o0 + col) = make_float2(oacc[j][0] * inv0, oacc[j][1] * inv0);
        *(float2*)(o1 + col) = make_float2(oacc[j][2] * inv1, oacc[j][3] * inv1);
    }
}

// ---------------- Launch ----------------
extern "C" void kernel_launch(void* const* d_in, const int* in_sizes, int n_in,
                              void* d_out, int out_size)
{
    const float* Xq  = (const float*)d_in[0];
    const float* Xkv = (const float*)d_in[1];
    const int*   qpos = (const int*)d_in[2];
    const int*   kpos = (const int*)d_in[3];
    const float* Wq  = (const float*)d_in[4];
    const float* Wk  = (const float*)d_in[5];
    const float* Wv  = (const float*)d_in[6];
    const float* Wo  = (const float*)d_in[7];
    float* out = (float*)d_out;

    float *qb, *kb, *vb, *ab;
    cudaGetSymbolAddress((void**)&qb, g_q);
    cudaGetSymbolAddress((void**)&kb, g_k);
    cudaGetSymbolAddress((void**)&vb, g_v);
    cudaGetSymbolAddress((void**)&ab, g_attn);

    const int SM1X = (128 * AP + 32 * BP) * (int)sizeof(float);          // 35840
    cudaFuncSetAttribute(gemm_bf3, cudaFuncAttributeMaxDynamicSharedMemorySize, G_SMEM);
    cudaFuncSetAttribute(mma_gemm1, cudaFuncAttributeMaxDynamicSharedMemorySize, SM1X);
    cudaFuncSetAttribute(attn_tc_kernel, cudaFuncAttributeMaxDynamicSharedMemorySize, A_SMEM);

    dim3 blk(256);
    // Q and K projections: 3-pass bf16 split (fp32-class precision)
    gemm_bf3<<<dim3(16, 16), blk, G_SMEM>>>(Xq,  Wq, qb, 2048, 2048, 2048);
    gemm_bf3<<<dim3(4,  16), blk, G_SMEM>>>(Xkv, Wk, kb, 2048, 512,  2048);
    // V projection: single-pass tf32
    mma_gemm1<<<dim3(4,  16), blk, SM1X>>>(Xkv, Wv, vb, 2048, 512,  2048);

    // RoPE on q and k
    rope_kernel<<<(B_*T_*NQ*64 + 255) / 256, 256>>>(qb, qpos, B_*T_*NQ*64, NQ);
    rope_kernel<<<(B_*S_*NKV*64 + 255) / 256, 256>>>(kb, kpos, B_*S_*NKV*64, NKV);

    // Attention (tensor-core flash, bf16 QK^T / tf32 PV)
    attn_tc_kernel<<<dim3(T_/128, NQ, B_), blk, A_SMEM>>>(qb, kb, vb, ab);

    // Output projection: single-pass tf32
    mma_gemm1<<<dim3(16, 16), blk, SM1X>>>(ab, Wo, out, 2048, 2048, 2048);
}

// round 5
// speedup vs baseline: 3.5607x; 1.2130x over previous
#include <cuda_runtime.h>
#include <cuda_bf16.h>
#include <cuda_fp16.h>
#include <cstdint>

#define B_  2
#define T_  1024
#define S_  1024
#define NQ  16
#define NKV 4
#define HD  128

// Scratch (allocation-free rule: __device__ globals)
__device__ float g_q[B_*T_*NQ*HD];      // (B,T,NQ,HD)
__device__ float g_k[B_*S_*NKV*HD];     // (B,S,NKV,HD)
__device__ float g_v[B_*S_*NKV*HD];
__device__ float g_attn[B_*T_*NQ*HD];

// ---------------------------------------------------------------------------
// helpers
// ---------------------------------------------------------------------------
__device__ __forceinline__ void mma_bf16(float d[4], const uint32_t a[4], const uint32_t b[2])
{
    asm volatile(
        "mma.sync.aligned.m16n8k16.row.col.f32.bf16.bf16.f32 "
        "{%0,%1,%2,%3}, {%4,%5,%6,%7}, {%8,%9}, {%0,%1,%2,%3};\n"
        : "+f"(d[0]), "+f"(d[1]), "+f"(d[2]), "+f"(d[3])
        : "r"(a[0]), "r"(a[1]), "r"(a[2]), "r"(a[3]), "r"(b[0]), "r"(b[1]));
}

__device__ __forceinline__ void mma_fp16(float d[4], const uint32_t a[4], const uint32_t b[2])
{
    asm volatile(
        "mma.sync.aligned.m16n8k16.row.col.f32.f16.f16.f32 "
        "{%0,%1,%2,%3}, {%4,%5,%6,%7}, {%8,%9}, {%0,%1,%2,%3};\n"
        : "+f"(d[0]), "+f"(d[1]), "+f"(d[2]), "+f"(d[3])
        : "r"(a[0]), "r"(a[1]), "r"(a[2]), "r"(a[3]), "r"(b[0]), "r"(b[1]));
}

__device__ __forceinline__ void ldsm_x4(uint32_t r[4], uint32_t addr) {
    asm volatile("ldmatrix.sync.aligned.m8n8.x4.shared.b16 {%0,%1,%2,%3}, [%4];"
                 : "=r"(r[0]), "=r"(r[1]), "=r"(r[2]), "=r"(r[3]) : "r"(addr));
}
__device__ __forceinline__ void ldsm_x2(uint32_t r[2], uint32_t addr) {
    asm volatile("ldmatrix.sync.aligned.m8n8.x2.shared.b16 {%0,%1}, [%2];"
                 : "=r"(r[0]), "=r"(r[1]) : "r"(addr));
}
__device__ __forceinline__ void ldsm_x2t(uint32_t r[2], uint32_t addr) {
    asm volatile("ldmatrix.sync.aligned.m8n8.x2.trans.shared.b16 {%0,%1}, [%2];"
                 : "=r"(r[0]), "=r"(r[1]) : "r"(addr));
}

// split two floats into packed bf16 hi / lo pairs
__device__ __forceinline__ void bf16_split2(float x, float y, uint32_t& hi, uint32_t& lo) {
    __nv_bfloat16 hx = __float2bfloat16(x);
    __nv_bfloat16 hy = __float2bfloat16(y);
    __nv_bfloat16 lx = __float2bfloat16(x - __bfloat162float(hx));
    __nv_bfloat16 ly = __float2bfloat16(y - __bfloat162float(hy));
    hi = (uint32_t)__bfloat16_as_ushort(hx) | ((uint32_t)__bfloat16_as_ushort(hy) << 16);
    lo = (uint32_t)__bfloat16_as_ushort(lx) | ((uint32_t)__bfloat16_as_ushort(ly) << 16);
}

__device__ __forceinline__ uint32_t fp16_pack2(float x, float y) {
    __half2 h = __floats2half2_rn(x, y);
    return *(uint32_t*)&h;
}

// ---------------------------------------------------------------------------
// bf16 3-pass GEMM (fp32-class accuracy): C[M,N] = A[M,K] @ B[K,N], row-major.
// CTA 128x128, BK=32, 256 threads (8 warps 2x4), warp tile 64x32. (R4, unchanged)
// ---------------------------------------------------------------------------
#define G_AH 0
#define G_AL 10240
#define G_BH 20480
#define G_BL 29184
#define G_SMEM 37888

__global__ void __launch_bounds__(256) gemm_bf3(
    const float* __restrict__ A, const float* __restrict__ Bm,
    float* __restrict__ C, int M, int N, int K)
{
    extern __shared__ char smraw[];
    const uint32_t sb = (uint32_t)__cvta_generic_to_shared(smraw);

    const int tid  = threadIdx.x;
    const int lane = tid & 31;
    const int warp = tid >> 5;
    const int grp  = lane >> 2;
    const int qid  = lane & 3;
    const int wm   = (warp >> 2) * 64;
    const int wn   = (warp & 3) * 32;
    const int row0 = blockIdx.y * 128;
    const int col0 = blockIdx.x * 128;

    float acc[4][4][4];
    #pragma unroll
    for (int i = 0; i < 4; i++)
        #pragma unroll
        for (int j = 0; j < 4; j++)
            #pragma unroll
            for (int c = 0; c < 4; c++) acc[i][j][c] = 0.f;

    float4 aReg[4], bReg[4];
    #pragma unroll
    for (int i = 0; i < 4; i++) {
        int idx = tid + i * 256;
        int ar = idx >> 3, ac = (idx & 7) << 2;
        aReg[i] = *(const float4*)(A + (size_t)(row0 + ar) * K + ac);
        int bk = idx >> 5, bn = (idx & 31) << 2;
        bReg[i] = *(const float4*)(Bm + (size_t)bk * N + col0 + bn);
    }

    for (int k0 = 0; k0 < K; k0 += 32) {
        #pragma unroll
        for (int i = 0; i < 4; i++) {
            int idx = tid + i * 256;
            int ar = idx >> 3, ac = (idx & 7) << 2;
            uint32_t h01, l01, h23, l23;
            bf16_split2(aReg[i].x, aReg[i].y, h01, l01);
            bf16_split2(aReg[i].z, aReg[i].w, h23, l23);
            int aoff = (ar * 40 + ac) << 1;
            *(uint2*)(smraw + G_AH + aoff) = make_uint2(h01, h23);
            *(uint2*)(smraw + G_AL + aoff) = make_uint2(l01, l23);

            int bk = idx >> 5, bn = (idx & 31) << 2;
            bf16_split2(bReg[i].x, bReg[i].y, h01, l01);
            bf16_split2(bReg[i].z, bReg[i].w, h23, l23);
            int boff = (bk * 136 + bn) << 1;
            *(uint2*)(smraw + G_BH + boff) = make_uint2(h01, h23);
            *(uint2*)(smraw + G_BL + boff) = make_uint2(l01, l23);
        }
        __syncthreads();

        if (k0 + 32 < K) {
            #pragma unroll
            for (int i = 0; i < 4; i++) {
                int idx = tid + i * 256;
                int ar = idx >> 3, ac = (idx & 7) << 2;
                aReg[i] = *(const float4*)(A + (size_t)(row0 + ar) * K + k0 + 32 + ac);
                int bk = idx >> 5, bn = (idx & 31) << 2;
                bReg[i] = *(const float4*)(Bm + (size_t)(k0 + 32 + bk) * N + col0 + bn);
            }
        }

        #pragma unroll
        for (int kk = 0; kk < 32; kk += 16) {
            uint32_t ah[4][4], al[4][4];
            #pragma unroll
            for (int im = 0; im < 4; im++) {
                int m = wm + im * 16 + (lane & 15);
                uint32_t ab = sb + G_AH + ((m * 40 + kk + ((lane >> 4) << 3)) << 1);
                ldsm_x4(ah[im], ab);
                ldsm_x4(al[im], ab + (G_AL - G_AH));
            }
            uint32_t bh[4][2], bl[4][2];
            #pragma unroll
            for (int in_ = 0; in_ < 4; in_++) {
                int kr = kk + (lane & 15);
                uint32_t bb = sb + G_BH + ((kr * 136 + wn + in_ * 8) << 1);
                ldsm_x2t(bh[in_], bb);
                ldsm_x2t(bl[in_], bb + (G_BL - G_BH));
            }
            #pragma unroll
            for (int im = 0; im < 4; im++)
                #pragma unroll
                for (int in_ = 0; in_ < 4; in_++) {
                    mma_bf16(acc[im][in_], ah[im], bh[in_]);
                    mma_bf16(acc[im][in_], ah[im], bl[in_]);
                    mma_bf16(acc[im][in_], al[im], bh[in_]);
                }
        }
        __syncthreads();
    }

    #pragma unroll
    for (int im = 0; im < 4; im++) {
        int r = row0 + wm + im * 16 + grp;
        #pragma unroll
        for (int in_ = 0; in_ < 4; in_++) {
            int nc = col0 + wn + in_ * 8 + 2 * qid;
            *(float2*)(C + (size_t)r * N + nc)       = make_float2(acc[im][in_][0], acc[im][in_][1]);
            *(float2*)(C + (size_t)(r + 8) * N + nc) = make_float2(acc[im][in_][2], acc[im][in_][3]);
        }
    }
}

// ---------------------------------------------------------------------------
// fp16 1-pass GEMM (tf32-class accuracy, k16): C[M,N] = A[M,K] @ B[K,N].
// Same tiling as gemm_bf3 but single hi buffer, half the MMAs.
// ---------------------------------------------------------------------------
#define F_AH 0
#define F_BH 10240
#define F_SMEM 18944

__global__ void __launch_bounds__(256) gemm_fp16(
    const float* __restrict__ A, const float* __restrict__ Bm,
    float* __restrict__ C, int M, int N, int K)
{
    extern __shared__ char smraw[];
    const uint32_t sb = (uint32_t)__cvta_generic_to_shared(smraw);

    const int tid  = threadIdx.x;
    const int lane = tid & 31;
    const int warp = tid >> 5;
    const int grp  = lane >> 2;
    const int qid  = lane & 3;
    const int wm   = (warp >> 2) * 64;
    const int wn   = (warp & 3) * 32;
    const int row0 = blockIdx.y * 128;
    const int col0 = blockIdx.x * 128;

    float acc[4][4][4];
    #pragma unroll
    for (int i = 0; i < 4; i++)
        #pragma unroll
        for (int j = 0; j < 4; j++)
            #pragma unroll
            for (int c = 0; c < 4; c++) acc[i][j][c] = 0.f;

    float4 aReg[4], bReg[4];
    #pragma unroll
    for (int i = 0; i < 4; i++) {
        int idx = tid + i * 256;
        int ar = idx >> 3, ac = (idx & 7) << 2;
        aReg[i] = *(const float4*)(A + (size_t)(row0 + ar) * K + ac);
        int bk = idx >> 5, bn = (idx & 31) << 2;
        bReg[i] = *(const float4*)(Bm + (size_t)bk * N + col0 + bn);
    }

    for (int k0 = 0; k0 < K; k0 += 32) {
        #pragma unroll
        for (int i = 0; i < 4; i++) {
            int idx = tid + i * 256;
            int ar = idx >> 3, ac = (idx & 7) << 2;
            int aoff = (ar * 40 + ac) << 1;
            *(uint2*)(smraw + F_AH + aoff) =
                make_uint2(fp16_pack2(aReg[i].x, aReg[i].y), fp16_pack2(aReg[i].z, aReg[i].w));
            int bk = idx >> 5, bn = (idx & 31) << 2;
            int boff = (bk * 136 + bn) << 1;
            *(uint2*)(smraw + F_BH + boff) =
                make_uint2(fp16_pack2(bReg[i].x, bReg[i].y), fp16_pack2(bReg[i].z, bReg[i].w));
        }
        __syncthreads();

        if (k0 + 32 < K) {
            #pragma unroll
            for (int i = 0; i < 4; i++) {
                int idx = tid + i * 256;
                int ar = idx >> 3, ac = (idx & 7) << 2;
                aReg[i] = *(const float4*)(A + (size_t)(row0 + ar) * K + k0 + 32 + ac);
                int bk = idx >> 5, bn = (idx & 31) << 2;
                bReg[i] = *(const float4*)(Bm + (size_t)(k0 + 32 + bk) * N + col0 + bn);
            }
        }

        #pragma unroll
        for (int kk = 0; kk < 32; kk += 16) {
            uint32_t ah[4][4];
            #pragma unroll
            for (int im = 0; im < 4; im++) {
                int m = wm + im * 16 + (lane & 15);
                ldsm_x4(ah[im], sb + F_AH + ((m * 40 + kk + ((lane >> 4) << 3)) << 1));
            }
            uint32_t bh[4][2];
            #pragma unroll
            for (int in_ = 0; in_ < 4; in_++) {
                int kr = kk + (lane & 15);
                ldsm_x2t(bh[in_], sb + F_BH + ((kr * 136 + wn + in_ * 8) << 1));
            }
            #pragma unroll
            for (int im = 0; im < 4; im++)
                #pragma unroll
                for (int in_ = 0; in_ < 4; in_++)
                    mma_fp16(acc[im][in_], ah[im], bh[in_]);
        }
        __syncthreads();
    }

    #pragma unroll
    for (int im = 0; im < 4; im++) {
        int r = row0 + wm + im * 16 + grp;
        #pragma unroll
        for (int in_ = 0; in_ < 4; in_++) {
            int nc = col0 + wn + in_ * 8 + 2 * qid;
            *(float2*)(C + (size_t)r * N + nc)       = make_float2(acc[im][in_][0], acc[im][in_][1]);
            *(float2*)(C + (size_t)(r + 8) * N + nc) = make_float2(acc[im][in_][2], acc[im][in_][3]);
        }
    }
}

// ---------------- RoPE (in-place): x (BL, Nh, HD), half = 64 ----------------
__global__ void rope_kernel(float* __restrict__ x, const int* __restrict__ pos,
                            int total, int Nh)
{
    int idx = blockIdx.x * blockDim.x + threadIdx.x;
    if (idx >= total) return;
    int i   = idx & 63;
    int bln = idx >> 6;
    int bl  = bln / Nh;
    float p    = (float)pos[bl];
    float frac = (float)i * (1.0f / 64.0f);
    float ts   = powf(10000.0f, frac);
    float ang  = p / ts;
    float si = sinf(ang), co = cosf(ang);
    float* base = x + (size_t)bln * HD;
    float x1 = base[i], x2 = base[i + 64];
    base[i]      = x1 * co - x2 * si;
    base[i + 64] = x2 * co + x1 * si;
}

// ---------------------------------------------------------------------------
// Tensor-core flash attention. CTA = 128 queries x 1 head, 8 warps,
// warp w owns rows [16w,16w+16). QK^T: 3-pass bf16. PV: 1-pass fp16 (LDSM).
// Smem (bytes): Qh 0 (34816), Ql 34816, Kh 69632 (17408), Kl 87040,
// Vs 104448 (fp16 [64][136] = 17408), Ps 121856 (fp16 [128][72] = 18432).
// ---------------------------------------------------------------------------
#define A_QH 0
#define A_QL 34816
#define A_KH 69632
#define A_KL 87040
#define A_VS 104448
#define A_PS 121856
#define A_SMEM 140288
#define PSH 72     // P stride in halves (144 B = 9*16B -> conflict-free LDSM)
#define VSH 136    // V stride in halves (272 B = 17*16B -> conflict-free LDSM)

__global__ void __launch_bounds__(256) attn_tc_kernel(
    const float* __restrict__ q, const float* __restrict__ k,
    const float* __restrict__ v, float* __restrict__ o)
{
    extern __shared__ char smraw[];
    const uint32_t sb = (uint32_t)__cvta_generic_to_shared(smraw);

    const int tid  = threadIdx.x;
    const int lane = tid & 31;
    const int warp = tid >> 5;
    const int grp  = lane >> 2;
    const int qid  = lane & 3;
    const int wm   = warp * 16;
    const int t0   = blockIdx.x * 128;
    const int n    = blockIdx.y;
    const int b    = blockIdx.z;
    const int kvh  = n >> 2;

    const float* Qg = q + ((size_t)(b * T_ + t0) * NQ  + n)   * HD;
    const float* Kg = k + ((size_t)(b * S_)      * NKV + kvh) * HD;
    const float* Vg = v + ((size_t)(b * S_)      * NKV + kvh) * HD;

    // Load + split Q tile [128][128] -> bf16 hi/lo, stride 136
    for (int f = tid; f < 128 * 32; f += 256) {
        int r = f >> 5, c4 = (f & 31) << 2;
        float4 a = *(const float4*)(Qg + (size_t)r * (NQ * HD) + c4);
        uint32_t h01, l01, h23, l23;
        bf16_split2(a.x, a.y, h01, l01);
        bf16_split2(a.z, a.w, h23, l23);
        int off = (r * 136 + c4) << 1;
        *(uint2*)(smraw + A_QH + off) = make_uint2(h01, h23);
        *(uint2*)(smraw + A_QL + off) = make_uint2(l01, l23);
    }

    float m0 = -1e30f, m1 = -1e30f, l0 = 0.f, l1 = 0.f;
    float oacc[16][4];
    #pragma unroll
    for (int j = 0; j < 16; j++)
        #pragma unroll
        for (int c = 0; c < 4; c++) oacc[j][c] = 0.f;

    const int rP0 = (wm + grp) * PSH;
    const int rP1 = (wm + grp + 8) * PSH;

    for (int s0 = 0; s0 < S_; s0 += 64) {
        __syncthreads();   // prev iter done reading K/V (also orders Q on iter 0)
        for (int f = tid; f < 64 * 32; f += 256) {
            int r = f >> 5, c4 = (f & 31) << 2;
            float4 a = *(const float4*)(Kg + (size_t)(s0 + r) * (NKV * HD) + c4);
            uint32_t h01, l01, h23, l23;
            bf16_split2(a.x, a.y, h01, l01);
            bf16_split2(a.z, a.w, h23, l23);
            int off = (r * 136 + c4) << 1;
            *(uint2*)(smraw + A_KH + off) = make_uint2(h01, h23);
            *(uint2*)(smraw + A_KL + off) = make_uint2(l01, l23);
            float4 vv = *(const float4*)(Vg + (size_t)(s0 + r) * (NKV * HD) + c4);
            *(uint2*)(smraw + A_VS + ((r * VSH + c4) << 1)) =
                make_uint2(fp16_pack2(vv.x, vv.y), fp16_pack2(vv.z, vv.w));
        }
        __syncthreads();

        // ---- S = Q K^T (3-pass bf16) ----
        float sacc[8][4];
        #pragma unroll
        for (int j = 0; j < 8; j++)
            #pragma unroll
            for (int c = 0; c < 4; c++) sacc[j][c] = 0.f;

        #pragma unroll
        for (int kk = 0; kk < 8; kk++) {
            const int col0h = kk * 16;
            uint32_t ah[4], al[4];
            {
                int m = wm + (lane & 15);
                uint32_t ab = sb + A_QH + ((m * 136 + col0h + ((lane >> 4) << 3)) << 1);
                ldsm_x4(ah, ab);
                ldsm_x4(al, ab + (A_QL - A_QH));
            }
            #pragma unroll
            for (int j = 0; j < 8; j++) {
                int row = j * 8 + (lane & 7);
                uint32_t bb = sb + A_KH + ((row * 136 + col0h + (lane & 8)) << 1);
                uint32_t bh[2], bl[2];
                ldsm_x2(bh, bb);
                ldsm_x2(bl, bb + (A_KL - A_KH));
                mma_bf16(sacc[j], ah, bh);
                mma_bf16(sacc[j], ah, bl);
                mma_bf16(sacc[j], al, bh);
            }
        }

        // ---- online softmax (rows grp / grp+8, quad-wide) ----
        float mx0 = -1e30f, mx1 = -1e30f;
        #pragma unroll
        for (int j = 0; j < 8; j++) {
            mx0 = fmaxf(mx0, fmaxf(sacc[j][0], sacc[j][1]));
            mx1 = fmaxf(mx1, fmaxf(sacc[j][2], sacc[j][3]));
        }
        #pragma unroll
        for (int off = 1; off < 4; off <<= 1) {
            mx0 = fmaxf(mx0, __shfl_xor_sync(0xffffffffu, mx0, off));
            mx1 = fmaxf(mx1, __shfl_xor_sync(0xffffffffu, mx1, off));
        }
        float mn0 = fmaxf(m0, mx0), mn1 = fmaxf(m1, mx1);
        float cr0 = __expf(m0 - mn0), cr1 = __expf(m1 - mn1);
        float ps0 = 0.f, ps1 = 0.f;
        #pragma unroll
        for (int j = 0; j < 8; j++) {
            float e0 = __expf(sacc[j][0] - mn0);
            float e1 = __expf(sacc[j][1] - mn0);
            float e2 = __expf(sacc[j][2] - mn1);
            float e3 = __expf(sacc[j][3] - mn1);
            ps0 += e0 + e1; ps1 += e2 + e3;
            *(uint32_t*)(smraw + A_PS + ((rP0 + j * 8 + 2 * qid) << 1)) = fp16_pack2(e0, e1);
            *(uint32_t*)(smraw + A_PS + ((rP1 + j * 8 + 2 * qid) << 1)) = fp16_pack2(e2, e3);
        }
        #pragma unroll
        for (int off = 1; off < 4; off <<= 1) {
            ps0 += __shfl_xor_sync(0xffffffffu, ps0, off);
            ps1 += __shfl_xor_sync(0xffffffffu, ps1, off);
        }
        l0 = l0 * cr0 + ps0; m0 = mn0;
        l1 = l1 * cr1 + ps1; m1 = mn1;
        #pragma unroll
        for (int j = 0; j < 16; j++) {
            oacc[j][0] *= cr0; oacc[j][1] *= cr0;
            oacc[j][2] *= cr1; oacc[j][3] *= cr1;
        }
        __syncwarp();   // P stores visible to whole warp before ldmatrix

        // ---- O += P V (fp16 1x, ldmatrix; P rows warp-private) ----
        #pragma unroll
        for (int kk = 0; kk < 4; kk++) {
            uint32_t pa[4];
            {
                int row = wm + (lane & 15);
                ldsm_x4(pa, sb + A_PS + ((row * PSH + kk * 16 + ((lane >> 4) << 3)) << 1));
            }
            #pragma unroll
            for (int j = 0; j < 16; j++) {
                uint32_t vb[2];
                int kr = kk * 16 + (lane & 15);
                ldsm_x2t(vb, sb + A_VS + ((kr * VSH + j * 8) << 1));
                mma_fp16(oacc[j], pa, vb);
            }
        }
    }

    // ---- epilogue ----
    float inv0 = 1.0f / l0, inv1 = 1.0f / l1;
    float* o0 = o + ((size_t)(b * T_ + t0 + wm + grp)     * NQ + n) * HD;
    float* o1 = o + ((size_t)(b * T_ + t0 + wm + grp + 8) * NQ + n) * HD;
    #pragma unroll
    for (int j = 0; j < 16; j++) {
        int col = j * 8 + 2 * qid;
        *(float2*)(o0 + col) = make_float2(oacc[j][0] * inv0, oacc[j][1] * inv0);
        *(float2*)(o1 + col) = make_float2(oacc[j][2] * inv1, oacc[j][3] * inv1);
    }
}

// ---------------- Launch ----------------
extern "C" void kernel_launch(void* const* d_in, const int* in_sizes, int n_in,
                              void* d_out, int out_size)
{
    const float* Xq  = (const float*)d_in[0];
    const float* Xkv = (const float*)d_in[1];
    const int*   qpos = (const int*)d_in[2];
    const int*   kpos = (const int*)d_in[3];
    const float* Wq  = (const float*)d_in[4];
    const float* Wk  = (const float*)d_in[5];
    const float* Wv  = (const float*)d_in[6];
    const float* Wo  = (const float*)d_in[7];
    float* out = (float*)d_out;

    float *qb, *kb, *vb, *ab;
    cudaGetSymbolAddress((void**)&qb, g_q);
    cudaGetSymbolAddress((void**)&kb, g_k);
    cudaGetSymbolAddress((void**)&vb, g_v);
    cudaGetSymbolAddress((void**)&ab, g_attn);

    cudaFuncSetAttribute(gemm_bf3, cudaFuncAttributeMaxDynamicSharedMemorySize, G_SMEM);
    cudaFuncSetAttribute(attn_tc_kernel, cudaFuncAttributeMaxDynamicSharedMemorySize, A_SMEM);

    dim3 blk(256);
    // Q and K projections: 3-pass bf16 split (fp32-class precision)
    gemm_bf3<<<dim3(16, 16), blk, G_SMEM>>>(Xq,  Wq, qb, 2048, 2048, 2048);
    gemm_bf3<<<dim3(4,  16), blk, G_SMEM>>>(Xkv, Wk, kb, 2048, 512,  2048);
    // V projection: 1-pass fp16 (tf32-class precision, half the MMAs)
    gemm_fp16<<<dim3(4,  16), blk, F_SMEM>>>(Xkv, Wv, vb, 2048, 512,  2048);

    // RoPE on q and k
    rope_kernel<<<(B_*T_*NQ*64 + 255) / 256, 256>>>(qb, qpos, B_*T_*NQ*64, NQ);
    rope_kernel<<<(B_*S_*NKV*64 + 255) / 256, 256>>>(kb, kpos, B_*S_*NKV*64, NKV);

    // Attention (tensor-core flash, bf16 QK^T / fp16 PV)
    attn_tc_kernel<<<dim3(T_/128, NQ, B_), blk, A_SMEM>>>(qb, kb, vb, ab);

    // Output projection: 1-pass fp16
    gemm_fp16<<<dim3(16, 16), blk, F_SMEM>>>(ab, Wo, out, 2048, 2048, 2048);
}

// round 7
// speedup vs baseline: 3.8391x; 1.0782x over previous
#include <cuda_runtime.h>
#include <cuda_bf16.h>
#include <cuda_fp16.h>
#include <cstdint>

#define B_  2
#define T_  1024
#define S_  1024
#define NQ  16
#define NKV 4
#define HD  128

// Scratch (allocation-free rule: __device__ globals)
__device__ float g_q[B_*T_*NQ*HD];      // (B,T,NQ,HD)
__device__ float g_k[B_*S_*NKV*HD];     // (B,S,NKV,HD)
__device__ float g_v[B_*S_*NKV*HD];
__device__ float g_attn[B_*T_*NQ*HD];

// ---------------------------------------------------------------------------
// helpers
// ---------------------------------------------------------------------------
__device__ __forceinline__ void mma_bf16(float d[4], const uint32_t a[4], const uint32_t b[2]) {
    asm volatile(
        "mma.sync.aligned.m16n8k16.row.col.f32.bf16.bf16.f32 "
        "{%0,%1,%2,%3}, {%4,%5,%6,%7}, {%8,%9}, {%0,%1,%2,%3};\n"
        : "+f"(d[0]), "+f"(d[1]), "+f"(d[2]), "+f"(d[3])
        : "r"(a[0]), "r"(a[1]), "r"(a[2]), "r"(a[3]), "r"(b[0]), "r"(b[1]));
}
__device__ __forceinline__ void mma_fp16(float d[4], const uint32_t a[4], const uint32_t b[2]) {
    asm volatile(
        "mma.sync.aligned.m16n8k16.row.col.f32.f16.f16.f32 "
        "{%0,%1,%2,%3}, {%4,%5,%6,%7}, {%8,%9}, {%0,%1,%2,%3};\n"
        : "+f"(d[0]), "+f"(d[1]), "+f"(d[2]), "+f"(d[3])
        : "r"(a[0]), "r"(a[1]), "r"(a[2]), "r"(a[3]), "r"(b[0]), "r"(b[1]));
}
__device__ __forceinline__ void ldsm_x4(uint32_t r[4], uint32_t addr) {
    asm volatile("ldmatrix.sync.aligned.m8n8.x4.shared.b16 {%0,%1,%2,%3}, [%4];"
                 : "=r"(r[0]), "=r"(r[1]), "=r"(r[2]), "=r"(r[3]) : "r"(addr));
}
__device__ __forceinline__ void ldsm_x4t(uint32_t r[4], uint32_t addr) {
    asm volatile("ldmatrix.sync.aligned.m8n8.x4.trans.shared.b16 {%0,%1,%2,%3}, [%4];"
                 : "=r"(r[0]), "=r"(r[1]), "=r"(r[2]), "=r"(r[3]) : "r"(addr));
}
__device__ __forceinline__ void ldsm_x2t(uint32_t r[2], uint32_t addr) {
    asm volatile("ldmatrix.sync.aligned.m8n8.x2.trans.shared.b16 {%0,%1}, [%2];"
                 : "=r"(r[0]), "=r"(r[1]) : "r"(addr));
}
__device__ __forceinline__ void bf16_split2(float x, float y, uint32_t& hi, uint32_t& lo) {
    __nv_bfloat16 hx = __float2bfloat16(x);
    __nv_bfloat16 hy = __float2bfloat16(y);
    __nv_bfloat16 lx = __float2bfloat16(x - __bfloat162float(hx));
    __nv_bfloat16 ly = __float2bfloat16(y - __bfloat162float(hy));
    hi = (uint32_t)__bfloat16_as_ushort(hx) | ((uint32_t)__bfloat16_as_ushort(hy) << 16);
    lo = (uint32_t)__bfloat16_as_ushort(lx) | ((uint32_t)__bfloat16_as_ushort(ly) << 16);
}
__device__ __forceinline__ uint32_t fp16_pack2(float x, float y) {
    __half2 h = __floats2half2_rn(x, y);
    return *(uint32_t*)&h;
}

// ---------------------------------------------------------------------------
// GEMM core: C[M,N] = A[M,K] @ B[K,N], row-major, CTA tile 128x128, BK=32.
// PASSES=3: bf16 hi/lo 3-term split. PASSES=1: 1-pass fp16.
// Smem (bytes): Ah 0 [128][40], (Al 10240), Bh (P3: 20480 / P1: 10240) [32][136], (Bl 29184).
// ---------------------------------------------------------------------------
template<int PASSES>
__device__ __forceinline__ void gemm_core(
    const float* __restrict__ A, const float* __restrict__ Bm, float* __restrict__ C,
    int N, int K, int row0, int col0, char* smraw)
{
    const uint32_t sb = (uint32_t)__cvta_generic_to_shared(smraw);
    constexpr int AHo = 0;
    constexpr int ALo = 10240;
    constexpr int BHo = (PASSES == 3) ? 20480 : 10240;
    constexpr int BLo = 29184;

    const int tid  = threadIdx.x;
    const int lane = tid & 31;
    const int warp = tid >> 5;
    const int grp  = lane >> 2;
    const int qid  = lane & 3;
    const int wm   = (warp >> 2) * 64;
    const int wn   = (warp & 3) * 32;

    float acc[4][4][4];
    #pragma unroll
    for (int i = 0; i < 4; i++)
        #pragma unroll
        for (int j = 0; j < 4; j++)
            #pragma unroll
            for (int c = 0; c < 4; c++) acc[i][j][c] = 0.f;

    float4 aReg[4], bReg[4];
    #pragma unroll
    for (int i = 0; i < 4; i++) {
        int idx = tid + i * 256;
        int ar = idx >> 3, ac = (idx & 7) << 2;
        aReg[i] = *(const float4*)(A + (size_t)(row0 + ar) * K + ac);
        int bk = idx >> 5, bn = (idx & 31) << 2;
        bReg[i] = *(const float4*)(Bm + (size_t)bk * N + col0 + bn);
    }

    for (int k0 = 0; k0 < K; k0 += 32) {
        #pragma unroll
        for (int i = 0; i < 4; i++) {
            int idx = tid + i * 256;
            int ar = idx >> 3, ac = (idx & 7) << 2;
            int aoff = (ar * 40 + ac) << 1;
            int bk = idx >> 5, bn = (idx & 31) << 2;
            int boff = (bk * 136 + bn) << 1;
            if (PASSES == 3) {
                uint32_t h01, l01, h23, l23;
                bf16_split2(aReg[i].x, aReg[i].y, h01, l01);
                bf16_split2(aReg[i].z, aReg[i].w, h23, l23);
                *(uint2*)(smraw + AHo + aoff) = make_uint2(h01, h23);
                *(uint2*)(smraw + ALo + aoff) = make_uint2(l01, l23);
                bf16_split2(bReg[i].x, bReg[i].y, h01, l01);
                bf16_split2(bReg[i].z, bReg[i].w, h23, l23);
                *(uint2*)(smraw + BHo + boff) = make_uint2(h01, h23);
                *(uint2*)(smraw + BLo + boff) = make_uint2(l01, l23);
            } else {
                *(uint2*)(smraw + AHo + aoff) =
                    make_uint2(fp16_pack2(aReg[i].x, aReg[i].y), fp16_pack2(aReg[i].z, aReg[i].w));
                *(uint2*)(smraw + BHo + boff) =
                    make_uint2(fp16_pack2(bReg[i].x, bReg[i].y), fp16_pack2(bReg[i].z, bReg[i].w));
            }
        }
        __syncthreads();

        if (k0 + 32 < K) {
            #pragma unroll
            for (int i = 0; i < 4; i++) {
                int idx = tid + i * 256;
                int ar = idx >> 3, ac = (idx & 7) << 2;
                aReg[i] = *(const float4*)(A + (size_t)(row0 + ar) * K + k0 + 32 + ac);
                int bk = idx >> 5, bn = (idx & 31) << 2;
                bReg[i] = *(const float4*)(Bm + (size_t)(k0 + 32 + bk) * N + col0 + bn);
            }
        }

        #pragma unroll
        for (int kk = 0; kk < 32; kk += 16) {
            uint32_t ah[4][4], al[4][4];
            #pragma unroll
            for (int im = 0; im < 4; im++) {
                int m = wm + im * 16 + (lane & 15);
                uint32_t ab = sb + AHo + ((m * 40 + kk + ((lane >> 4) << 3)) << 1);
                ldsm_x4(ah[im], ab);
                if (PASSES == 3) ldsm_x4(al[im], ab + (ALo - AHo));
            }
            uint32_t bh[4][2], bl[4][2];
            #pragma unroll
            for (int in_ = 0; in_ < 4; in_++) {
                int kr = kk + (lane & 15);
                uint32_t bb = sb + BHo + ((kr * 136 + wn + in_ * 8) << 1);
                ldsm_x2t(bh[in_], bb);
                if (PASSES == 3) ldsm_x2t(bl[in_], bb + (BLo - BHo));
            }
            #pragma unroll
            for (int im = 0; im < 4; im++)
                #pragma unroll
                for (int in_ = 0; in_ < 4; in_++) {
                    if (PASSES == 3) {
                        mma_bf16(acc[im][in_], ah[im], bh[in_]);
                        mma_bf16(acc[im][in_], ah[im], bl[in_]);
                        mma_bf16(acc[im][in_], al[im], bh[in_]);
                    } else {
                        mma_fp16(acc[im][in_], ah[im], bh[in_]);
                    }
                }
        }
        __syncthreads();
    }

    #pragma unroll
    for (int im = 0; im < 4; im++) {
        int r = row0 + wm + im * 16 + grp;
        #pragma unroll
        for (int in_ = 0; in_ < 4; in_++) {
            int nc = col0 + wn + in_ * 8 + 2 * qid;
            *(float2*)(C + (size_t)r * N + nc)       = make_float2(acc[im][in_][0], acc[im][in_][1]);
            *(float2*)(C + (size_t)(r + 8) * N + nc) = make_float2(acc[im][in_][2], acc[im][in_][3]);
        }
    }
}

// Merged Q/K/V projections in ONE launch. grid = (24, 16):
//   bx [0,16): Q-proj (bf16-3x, N=2048); [16,20): K-proj (bf16-3x, N=512);
//   [20,24): V-proj (fp16-1x, N=512).
__global__ void __launch_bounds__(256) proj_qkv(
    const float* __restrict__ Xq, const float* __restrict__ Wq, float* __restrict__ Cq,
    const float* __restrict__ Xkv, const float* __restrict__ Wk, float* __restrict__ Ck,
    const float* __restrict__ Wv, float* __restrict__ Cv)
{
    extern __shared__ char smraw[];
    const int bx = blockIdx.x;
    const int row0 = blockIdx.y * 128;
    if (bx < 16)
        gemm_core<3>(Xq, Wq, Cq, 2048, 2048, row0, bx * 128, smraw);
    else if (bx < 20)
        gemm_core<3>(Xkv, Wk, Ck, 512, 2048, row0, (bx - 16) * 128, smraw);
    else
        gemm_core<1>(Xkv, Wv, Cv, 512, 2048, row0, (bx - 20) * 128, smraw);
}

// Output projection (fp16 1-pass)
__global__ void __launch_bounds__(256) gemm_o(
    const float* __restrict__ A, const float* __restrict__ Bm, float* __restrict__ C)
{
    extern __shared__ char smraw[];
    gemm_core<1>(A, Bm, C, 2048, 2048, blockIdx.y * 128, blockIdx.x * 128, smraw);
}

// ---------------- RoPE (in-place): x (BL, Nh, HD), half = 64 ----------------
__global__ void rope_kernel(float* __restrict__ x, const int* __restrict__ pos,
                            int total, int Nh)
{
    int idx = blockIdx.x * blockDim.x + threadIdx.x;
    if (idx >= total) return;
    int i   = idx & 63;
    int bln = idx >> 6;
    int bl  = bln / Nh;
    float p    = (float)pos[bl];
    float frac = (float)i * (1.0f / 64.0f);
    float ts   = powf(10000.0f, frac);
    float ang  = p / ts;
    float si = sinf(ang), co = cosf(ang);
    float* base = x + (size_t)bln * HD;
    float x1 = base[i], x2 = base[i + 64];
    base[i]      = x1 * co - x2 * si;
    base[i + 64] = x2 * co + x1 * si;
}

// ---------------------------------------------------------------------------
// Tensor-core flash attention. CTA = 128 queries x 1 head, 8 warps,
// warp w owns rows [16w,16w+16). QK^T: 3-pass bf16. PV: 1-pass fp16.
// KV double-buffered, ONE __syncthreads per KV block. LDSM .x4 everywhere.
// Smem (bytes): QH 0 (34816), QL 34816, KV 69632 (2 bufs x 52224:
//   KH +0, KL +17408, VS(fp16) +34816), PS 174080 (fp16 [128][72] = 18432).
// Total 192512.
// ---------------------------------------------------------------------------
#define A_QH 0
#define A_QL 34816
#define A_KV 69632
#define KVSTRIDE 52224
#define A_PS 174080
#define A_SMEM 192512
#define PSH 72
#define VSH 136

__global__ void __launch_bounds__(256) attn_tc_kernel(
    const float* __restrict__ q, const float* __restrict__ k,
    const float* __restrict__ v, float* __restrict__ o)
{
    extern __shared__ char smraw[];
    const uint32_t sb = (uint32_t)__cvta_generic_to_shared(smraw);

    const int tid  = threadIdx.x;
    const int lane = tid & 31;
    const int warp = tid >> 5;
    const int grp  = lane >> 2;
    const int qid  = lane & 3;
    const int wm   = warp * 16;
    const int t0   = blockIdx.x * 128;
    const int n    = blockIdx.y;
    const int b    = blockIdx.z;
    const int kvh  = n >> 2;

    const float* Qg = q + ((size_t)(b * T_ + t0) * NQ  + n)   * HD;
    const float* Kg = k + ((size_t)(b * S_)      * NKV + kvh) * HD;
    const float* Vg = v + ((size_t)(b * S_)      * NKV + kvh) * HD;

    // Load + split Q tile [128][128] -> bf16 hi/lo, stride 136
    for (int f = tid; f < 128 * 32; f += 256) {
        int r = f >> 5, c4 = (f & 31) << 2;
        float4 a = *(const float4*)(Qg + (size_t)r * (NQ * HD) + c4);
        uint32_t h01, l01, h23, l23;
        bf16_split2(a.x, a.y, h01, l01);
        bf16_split2(a.z, a.w, h23, l23);
        int off = (r * 136 + c4) << 1;
        *(uint2*)(smraw + A_QH + off) = make_uint2(h01, h23);
        *(uint2*)(smraw + A_QL + off) = make_uint2(l01, l23);
    }
    // Fill KV block 0 into buffer 0
    for (int f = tid; f < 64 * 32; f += 256) {
        int r = f >> 5, c4 = (f & 31) << 2;
        float4 a = *(const float4*)(Kg + (size_t)r * (NKV * HD) + c4);
        uint32_t h01, l01, h23, l23;
        bf16_split2(a.x, a.y, h01, l01);
        bf16_split2(a.z, a.w, h23, l23);
        int off = (r * 136 + c4) << 1;
        *(uint2*)(smraw + A_KV + off)         = make_uint2(h01, h23);
        *(uint2*)(smraw + A_KV + 17408 + off) = make_uint2(l01, l23);
        float4 vv = *(const float4*)(Vg + (size_t)r * (NKV * HD) + c4);
        *(uint2*)(smraw + A_KV + 34816 + ((r * VSH + c4) << 1)) =
            make_uint2(fp16_pack2(vv.x, vv.y), fp16_pack2(vv.z, vv.w));
    }
    __syncthreads();

    float m0 = -1e30f, m1 = -1e30f, l0 = 0.f, l1 = 0.f;
    float oacc[16][4];
    #pragma unroll
    for (int j = 0; j < 16; j++)
        #pragma unroll
        for (int c = 0; c < 4; c++) oacc[j][c] = 0.f;

    const int rP0 = (wm + grp) * PSH;
    const int rP1 = (wm + grp + 8) * PSH;

    for (int blk = 0; blk < 16; blk++) {
        const uint32_t kvb = sb + A_KV + (uint32_t)(blk & 1) * KVSTRIDE;

        // ---- S = Q K^T (3-pass bf16, K fragments via ldsm.x4 pairs) ----
        float sacc[8][4];
        #pragma unroll
        for (int j = 0; j < 8; j++)
            #pragma unroll
            for (int c = 0; c < 4; c++) sacc[j][c] = 0.f;

        #pragma unroll
        for (int kk = 0; kk < 8; kk++) {
            const int col0h = kk * 16;
            uint32_t ah[4], al[4];
            {
                int m = wm + (lane & 15);
                uint32_t ab = sb + A_QH + ((m * 136 + col0h + ((lane >> 4) << 3)) << 1);
                ldsm_x4(ah, ab);
                ldsm_x4(al, ab + (A_QL - A_QH));
            }
            #pragma unroll
            for (int j2 = 0; j2 < 4; j2++) {
                int row = (j2 * 2 + (lane >> 4)) * 8 + (lane & 7);
                uint32_t bb = kvb + ((row * 136 + col0h + (lane & 8)) << 1);
                uint32_t bh4[4], bl4[4];
                ldsm_x4(bh4, bb);
                ldsm_x4(bl4, bb + 17408);
                mma_bf16(sacc[2*j2],   ah, bh4);
                mma_bf16(sacc[2*j2],   ah, bl4);
                mma_bf16(sacc[2*j2],   al, bh4);
                mma_bf16(sacc[2*j2+1], ah, bh4 + 2);
                mma_bf16(sacc[2*j2+1], ah, bl4 + 2);
                mma_bf16(sacc[2*j2+1], al, bh4 + 2);
            }
        }

        // ---- online softmax (rows grp / grp+8, quad-wide) ----
        float mx0 = -1e30f, mx1 = -1e30f;
        #pragma unroll
        for (int j = 0; j < 8; j++) {
            mx0 = fmaxf(mx0, fmaxf(sacc[j][0], sacc[j][1]));
            mx1 = fmaxf(mx1, fmaxf(sacc[j][2], sacc[j][3]));
        }
        #pragma unroll
        for (int off = 1; off < 4; off <<= 1) {
            mx0 = fmaxf(mx0, __shfl_xor_sync(0xffffffffu, mx0, off));
            mx1 = fmaxf(mx1, __shfl_xor_sync(0xffffffffu, mx1, off));
        }
        float mn0 = fmaxf(m0, mx0), mn1 = fmaxf(m1, mx1);
        float cr0 = __expf(m0 - mn0), cr1 = __expf(m1 - mn1);
        float ps0 = 0.f, ps1 = 0.f;
        #pragma unroll
        for (int j = 0; j < 8; j++) {
            float e0 = __expf(sacc[j][0] - mn0);
            float e1 = __expf(sacc[j][1] - mn0);
            float e2 = __expf(sacc[j][2] - mn1);
            float e3 = __expf(sacc[j][3] - mn1);
            ps0 += e0 + e1; ps1 += e2 + e3;
            *(uint32_t*)(smraw + A_PS + ((rP0 + j * 8 + 2 * qid) << 1)) = fp16_pack2(e0, e1);
            *(uint32_t*)(smraw + A_PS + ((rP1 + j * 8 + 2 * qid) << 1)) = fp16_pack2(e2, e3);
        }
        #pragma unroll
        for (int off = 1; off < 4; off <<= 1) {
            ps0 += __shfl_xor_sync(0xffffffffu, ps0, off);
            ps1 += __shfl_xor_sync(0xffffffffu, ps1, off);
        }
        l0 = l0 * cr0 + ps0; m0 = mn0;
        l1 = l1 * cr1 + ps1; m1 = mn1;
        #pragma unroll
        for (int j = 0; j < 16; j++) {
            oacc[j][0] *= cr0; oacc[j][1] *= cr0;
            oacc[j][2] *= cr1; oacc[j][3] *= cr1;
        }
        __syncwarp();   // P stores visible to whole warp before ldmatrix

        // ---- O += P V (fp16, V fragments via ldsm.x4.trans pairs) ----
        #pragma unroll
        for (int kk = 0; kk < 4; kk++) {
            uint32_t pa[4];
            {
                int row = wm + (lane & 15);
                ldsm_x4(pa, sb + A_PS + ((row * PSH + kk * 16 + ((lane >> 4) << 3)) << 1));
            }
            #pragma unroll
            for (int j2 = 0; j2 < 8; j2++) {
                int kr  = kk * 16 + (lane & 15);
                int col = (j2 * 2 + (lane >> 4)) * 8;
                uint32_t vb4[4];
                ldsm_x4t(vb4, kvb + 34816 + ((kr * VSH + col) << 1));
                mma_fp16(oacc[2*j2],     pa, vb4);
                mma_fp16(oacc[2*j2 + 1], pa, vb4 + 2);
            }
        }

        // ---- fill next KV block into the other buffer ----
        if (blk < 15) {
            const int s0n = (blk + 1) * 64;
            char* dst = smraw + A_KV + ((blk + 1) & 1) * KVSTRIDE;
            for (int f = tid; f < 64 * 32; f += 256) {
                int r = f >> 5, c4 = (f & 31) << 2;
                float4 a = *(const float4*)(Kg + (size_t)(s0n + r) * (NKV * HD) + c4);
                uint32_t h01, l01, h23, l23;
                bf16_split2(a.x, a.y, h01, l01);
                bf16_split2(a.z, a.w, h23, l23);
                int off = (r * 136 + c4) << 1;
                *(uint2*)(dst + off)         = make_uint2(h01, h23);
                *(uint2*)(dst + 17408 + off) = make_uint2(l01, l23);
                float4 vv = *(const float4*)(Vg + (size_t)(s0n + r) * (NKV * HD) + c4);
                *(uint2*)(dst + 34816 + ((r * VSH + c4) << 1)) =
                    make_uint2(fp16_pack2(vv.x, vv.y), fp16_pack2(vv.z, vv.w));
            }
        }
        __syncthreads();
    }

    // ---- epilogue ----
    float inv0 = 1.0f / l0, inv1 = 1.0f / l1;
    float* o0 = o + ((size_t)(b * T_ + t0 + wm + grp)     * NQ + n) * HD;
    float* o1 = o + ((size_t)(b * T_ + t0 + wm + grp + 8) * NQ + n) * HD;
    #pragma unroll
    for (int j = 0; j < 16; j++) {
        int col = j * 8 + 2 * qid;
        *(float2*)(o0 + col) = make_float2(oacc[j][0] * inv0, oacc[j][1] * inv0);
        *(float2*)(o1 + col) = make_float2(oacc[j][2] * inv1, oacc[j][3] * inv1);
    }
}

// ---------------- Launch ----------------
extern "C" void kernel_launch(void* const* d_in, const int* in_sizes, int n_in,
                              void* d_out, int out_size)
{
    const float* Xq  = (const float*)d_in[0];
    const float* Xkv = (const float*)d_in[1];
    const int*   qpos = (const int*)d_in[2];
    const int*   kpos = (const int*)d_in[3];
    const float* Wq  = (const float*)d_in[4];
    const float* Wk  = (const float*)d_in[5];
    const float* Wv  = (const float*)d_in[6];
    const float* Wo  = (const float*)d_in[7];
    float* out = (float*)d_out;

    float *qb, *kb, *vb, *ab;
    cudaGetSymbolAddress((void**)&qb, g_q);
    cudaGetSymbolAddress((void**)&kb, g_k);
    cudaGetSymbolAddress((void**)&vb, g_v);
    cudaGetSymbolAddress((void**)&ab, g_attn);

    const int P_SMEM = 37888;   // bf3 layout (fp16 path uses a subset)
    const int O_SMEM = 18944;
    cudaFuncSetAttribute(proj_qkv, cudaFuncAttributeMaxDynamicSharedMemorySize, P_SMEM);
    cudaFuncSetAttribute(gemm_o, cudaFuncAttributeMaxDynamicSharedMemorySize, O_SMEM);
    cudaFuncSetAttribute(attn_tc_kernel, cudaFuncAttributeMaxDynamicSharedMemorySize, A_SMEM);

    // Q/K/V projections in one launch
    proj_qkv<<<dim3(24, 16), 256, P_SMEM>>>(Xq, Wq, qb, Xkv, Wk, kb, Wv, vb);

    // RoPE on q and k
    rope_kernel<<<(B_*T_*NQ*64 + 255) / 256, 256>>>(qb, qpos, B_*T_*NQ*64, NQ);
    rope_kernel<<<(B_*S_*NKV*64 + 255) / 256, 256>>>(kb, kpos, B_*S_*NKV*64, NKV);

    // Attention (tensor-core flash, bf16 QK^T / fp16 PV, double-buffered KV)
    attn_tc_kernel<<<dim3(T_/128, NQ, B_), 256, A_SMEM>>>(qb, kb, vb, ab);

    // Output projection
    gemm_o<<<dim3(16, 16), 256, O_SMEM>>>(ab, Wo, out);
}

// round 8
// speedup vs baseline: 4.1542x; 1.0821x over previous
#include <cuda_runtime.h>
#include <cuda_bf16.h>
#include <cuda_fp16.h>
#include <cstdint>

#define B_  2
#define T_  1024
#define S_  1024
#define NQ  16
#define NKV 4
#define HD  128

// Scratch (allocation-free rule: __device__ globals)
__device__ float g_q[B_*T_*NQ*HD];      // (B,T,NQ,HD)
__device__ float g_k[B_*S_*NKV*HD];     // (B,S,NKV,HD)
__device__ float g_v[B_*S_*NKV*HD];
__device__ float g_attn[B_*T_*NQ*HD];

// ---------------------------------------------------------------------------
// helpers
// ---------------------------------------------------------------------------
__device__ __forceinline__ void mma_bf16(float d[4], const uint32_t a[4], const uint32_t b[2]) {
    asm volatile(
        "mma.sync.aligned.m16n8k16.row.col.f32.bf16.bf16.f32 "
        "{%0,%1,%2,%3}, {%4,%5,%6,%7}, {%8,%9}, {%0,%1,%2,%3};\n"
        : "+f"(d[0]), "+f"(d[1]), "+f"(d[2]), "+f"(d[3])
        : "r"(a[0]), "r"(a[1]), "r"(a[2]), "r"(a[3]), "r"(b[0]), "r"(b[1]));
}
__device__ __forceinline__ void mma_fp16(float d[4], const uint32_t a[4], const uint32_t b[2]) {
    asm volatile(
        "mma.sync.aligned.m16n8k16.row.col.f32.f16.f16.f32 "
        "{%0,%1,%2,%3}, {%4,%5,%6,%7}, {%8,%9}, {%0,%1,%2,%3};\n"
        : "+f"(d[0]), "+f"(d[1]), "+f"(d[2]), "+f"(d[3])
        : "r"(a[0]), "r"(a[1]), "r"(a[2]), "r"(a[3]), "r"(b[0]), "r"(b[1]));
}
__device__ __forceinline__ void ldsm_x4(uint32_t r[4], uint32_t addr) {
    asm volatile("ldmatrix.sync.aligned.m8n8.x4.shared.b16 {%0,%1,%2,%3}, [%4];"
                 : "=r"(r[0]), "=r"(r[1]), "=r"(r[2]), "=r"(r[3]) : "r"(addr));
}
__device__ __forceinline__ void ldsm_x4t(uint32_t r[4], uint32_t addr) {
    asm volatile("ldmatrix.sync.aligned.m8n8.x4.trans.shared.b16 {%0,%1,%2,%3}, [%4];"
                 : "=r"(r[0]), "=r"(r[1]), "=r"(r[2]), "=r"(r[3]) : "r"(addr));
}
__device__ __forceinline__ void ldsm_x2t(uint32_t r[2], uint32_t addr) {
    asm volatile("ldmatrix.sync.aligned.m8n8.x2.trans.shared.b16 {%0,%1}, [%2];"
                 : "=r"(r[0]), "=r"(r[1]) : "r"(addr));
}
__device__ __forceinline__ void bf16_split2(float x, float y, uint32_t& hi, uint32_t& lo) {
    __nv_bfloat16 hx = __float2bfloat16(x);
    __nv_bfloat16 hy = __float2bfloat16(y);
    __nv_bfloat16 lx = __float2bfloat16(x - __bfloat162float(hx));
    __nv_bfloat16 ly = __float2bfloat16(y - __bfloat162float(hy));
    hi = (uint32_t)__bfloat16_as_ushort(hx) | ((uint32_t)__bfloat16_as_ushort(hy) << 16);
    lo = (uint32_t)__bfloat16_as_ushort(lx) | ((uint32_t)__bfloat16_as_ushort(ly) << 16);
}
__device__ __forceinline__ uint32_t fp16_pack2(float x, float y) {
    __half2 h = __floats2half2_rn(x, y);
    return *(uint32_t*)&h;
}

// ---------------------------------------------------------------------------
// GEMM core (unchanged from R7): C[M,N] = A[M,K] @ B[K,N], CTA 128x128, BK=32.
// ---------------------------------------------------------------------------
template<int PASSES>
__device__ __forceinline__ void gemm_core(
    const float* __restrict__ A, const float* __restrict__ Bm, float* __restrict__ C,
    int N, int K, int row0, int col0, char* smraw)
{
    const uint32_t sb = (uint32_t)__cvta_generic_to_shared(smraw);
    constexpr int AHo = 0;
    constexpr int ALo = 10240;
    constexpr int BHo = (PASSES == 3) ? 20480 : 10240;
    constexpr int BLo = 29184;

    const int tid  = threadIdx.x;
    const int lane = tid & 31;
    const int warp = tid >> 5;
    const int grp  = lane >> 2;
    const int qid  = lane & 3;
    const int wm   = (warp >> 2) * 64;
    const int wn   = (warp & 3) * 32;

    float acc[4][4][4];
    #pragma unroll
    for (int i = 0; i < 4; i++)
        #pragma unroll
        for (int j = 0; j < 4; j++)
            #pragma unroll
            for (int c = 0; c < 4; c++) acc[i][j][c] = 0.f;

    float4 aReg[4], bReg[4];
    #pragma unroll
    for (int i = 0; i < 4; i++) {
        int idx = tid + i * 256;
        int ar = idx >> 3, ac = (idx & 7) << 2;
        aReg[i] = *(const float4*)(A + (size_t)(row0 + ar) * K + ac);
        int bk = idx >> 5, bn = (idx & 31) << 2;
        bReg[i] = *(const float4*)(Bm + (size_t)bk * N + col0 + bn);
    }

    for (int k0 = 0; k0 < K; k0 += 32) {
        #pragma unroll
        for (int i = 0; i < 4; i++) {
            int idx = tid + i * 256;
            int ar = idx >> 3, ac = (idx & 7) << 2;
            int aoff = (ar * 40 + ac) << 1;
            int bk = idx >> 5, bn = (idx & 31) << 2;
            int boff = (bk * 136 + bn) << 1;
            if (PASSES == 3) {
                uint32_t h01, l01, h23, l23;
                bf16_split2(aReg[i].x, aReg[i].y, h01, l01);
                bf16_split2(aReg[i].z, aReg[i].w, h23, l23);
                *(uint2*)(smraw + AHo + aoff) = make_uint2(h01, h23);
                *(uint2*)(smraw + ALo + aoff) = make_uint2(l01, l23);
                bf16_split2(bReg[i].x, bReg[i].y, h01, l01);
                bf16_split2(bReg[i].z, bReg[i].w, h23, l23);
                *(uint2*)(smraw + BHo + boff) = make_uint2(h01, h23);
                *(uint2*)(smraw + BLo + boff) = make_uint2(l01, l23);
            } else {
                *(uint2*)(smraw + AHo + aoff) =
                    make_uint2(fp16_pack2(aReg[i].x, aReg[i].y), fp16_pack2(aReg[i].z, aReg[i].w));
                *(uint2*)(smraw + BHo + boff) =
                    make_uint2(fp16_pack2(bReg[i].x, bReg[i].y), fp16_pack2(bReg[i].z, bReg[i].w));
            }
        }
        __syncthreads();

        if (k0 + 32 < K) {
            #pragma unroll
            for (int i = 0; i < 4; i++) {
                int idx = tid + i * 256;
                int ar = idx >> 3, ac = (idx & 7) << 2;
                aReg[i] = *(const float4*)(A + (size_t)(row0 + ar) * K + k0 + 32 + ac);
                int bk = idx >> 5, bn = (idx & 31) << 2;
                bReg[i] = *(const float4*)(Bm + (size_t)(k0 + 32 + bk) * N + col0 + bn);
            }
        }

        #pragma unroll
        for (int kk = 0; kk < 32; kk += 16) {
            uint32_t ah[4][4], al[4][4];
            #pragma unroll
            for (int im = 0; im < 4; im++) {
                int m = wm + im * 16 + (lane & 15);
                uint32_t ab = sb + AHo + ((m * 40 + kk + ((lane >> 4) << 3)) << 1);
                ldsm_x4(ah[im], ab);
                if (PASSES == 3) ldsm_x4(al[im], ab + (ALo - AHo));
            }
            uint32_t bh[4][2], bl[4][2];
            #pragma unroll
            for (int in_ = 0; in_ < 4; in_++) {
                int kr = kk + (lane & 15);
                uint32_t bb = sb + BHo + ((kr * 136 + wn + in_ * 8) << 1);
                ldsm_x2t(bh[in_], bb);
                if (PASSES == 3) ldsm_x2t(bl[in_], bb + (BLo - BHo));
            }
            #pragma unroll
            for (int im = 0; im < 4; im++)
                #pragma unroll
                for (int in_ = 0; in_ < 4; in_++) {
                    if (PASSES == 3) {
                        mma_bf16(acc[im][in_], ah[im], bh[in_]);
                        mma_bf16(acc[im][in_], ah[im], bl[in_]);
                        mma_bf16(acc[im][in_], al[im], bh[in_]);
                    } else {
                        mma_fp16(acc[im][in_], ah[im], bh[in_]);
                    }
                }
        }
        __syncthreads();
    }

    #pragma unroll
    for (int im = 0; im < 4; im++) {
        int r = row0 + wm + im * 16 + grp;
        #pragma unroll
        for (int in_ = 0; in_ < 4; in_++) {
            int nc = col0 + wn + in_ * 8 + 2 * qid;
            *(float2*)(C + (size_t)r * N + nc)       = make_float2(acc[im][in_][0], acc[im][in_][1]);
            *(float2*)(C + (size_t)(r + 8) * N + nc) = make_float2(acc[im][in_][2], acc[im][in_][3]);
        }
    }
}

__global__ void __launch_bounds__(256) proj_qkv(
    const float* __restrict__ Xq, const float* __restrict__ Wq, float* __restrict__ Cq,
    const float* __restrict__ Xkv, const float* __restrict__ Wk, float* __restrict__ Ck,
    const float* __restrict__ Wv, float* __restrict__ Cv)
{
    extern __shared__ char smraw[];
    const int bx = blockIdx.x;
    const int row0 = blockIdx.y * 128;
    if (bx < 16)
        gemm_core<3>(Xq, Wq, Cq, 2048, 2048, row0, bx * 128, smraw);
    else if (bx < 20)
        gemm_core<3>(Xkv, Wk, Ck, 512, 2048, row0, (bx - 16) * 128, smraw);
    else
        gemm_core<1>(Xkv, Wv, Cv, 512, 2048, row0, (bx - 20) * 128, smraw);
}

__global__ void __launch_bounds__(256) gemm_o(
    const float* __restrict__ A, const float* __restrict__ Bm, float* __restrict__ C)
{
    extern __shared__ char smraw[];
    gemm_core<1>(A, Bm, C, 2048, 2048, blockIdx.y * 128, blockIdx.x * 128, smraw);
}

// ---------------- RoPE (in-place): x (BL, Nh, HD), half = 64 ----------------
__global__ void rope_kernel(float* __restrict__ x, const int* __restrict__ pos,
                            int total, int Nh)
{
    int idx = blockIdx.x * blockDim.x + threadIdx.x;
    if (idx >= total) return;
    int i   = idx & 63;
    int bln = idx >> 6;
    int bl  = bln / Nh;
    float p    = (float)pos[bl];
    float frac = (float)i * (1.0f / 64.0f);
    float ts   = powf(10000.0f, frac);
    float ang  = p / ts;
    float si = sinf(ang), co = cosf(ang);
    float* base = x + (size_t)bln * HD;
    float x1 = base[i], x2 = base[i + 64];
    base[i]      = x1 * co - x2 * si;
    base[i + 64] = x2 * co + x1 * si;
}

// ---------------------------------------------------------------------------
// Flash attention v2: CTA = 128 queries x 1 head, 8 warps, occ 2 CTAs/SM.
// KV block 32, single-buffered. QK^T: 3-pass bf16. PV: fp16 with A-fragments
// built DIRECTLY from softmax registers (no P smem).
// Smem: QH 0 (34816), QL 34816, KH 69632 (8704), KL 78336, VS 87040 (8704).
// Total 95744 -> 2 CTAs/SM.
// ---------------------------------------------------------------------------
#define A_QH 0
#define A_QL 34816
#define A_KH 69632
#define A_KL 78336
#define A_VS 87040
#define A_SMEM 95744
#define VSH 136

__global__ void __launch_bounds__(256, 2) attn_tc_kernel(
    const float* __restrict__ q, const float* __restrict__ k,
    const float* __restrict__ v, float* __restrict__ o)
{
    extern __shared__ char smraw[];
    const uint32_t sb = (uint32_t)__cvta_generic_to_shared(smraw);

    const int tid  = threadIdx.x;
    const int lane = tid & 31;
    const int warp = tid >> 5;
    const int grp  = lane >> 2;
    const int qid  = lane & 3;
    const int wm   = warp * 16;
    const int t0   = blockIdx.x * 128;
    const int n    = blockIdx.y;
    const int b    = blockIdx.z;
    const int kvh  = n >> 2;

    const float* Qg = q + ((size_t)(b * T_ + t0) * NQ  + n)   * HD;
    const float* Kg = k + ((size_t)(b * S_)      * NKV + kvh) * HD;
    const float* Vg = v + ((size_t)(b * S_)      * NKV + kvh) * HD;

    // Load + split Q tile [128][128] -> bf16 hi/lo, stride 136 halves
    for (int f = tid; f < 128 * 32; f += 256) {
        int r = f >> 5, c4 = (f & 31) << 2;
        float4 a = *(const float4*)(Qg + (size_t)r * (NQ * HD) + c4);
        uint32_t h01, l01, h23, l23;
        bf16_split2(a.x, a.y, h01, l01);
        bf16_split2(a.z, a.w, h23, l23);
        int off = (r * 136 + c4) << 1;
        *(uint2*)(smraw + A_QH + off) = make_uint2(h01, h23);
        *(uint2*)(smraw + A_QL + off) = make_uint2(l01, l23);
    }

    float m0 = -1e30f, m1 = -1e30f, l0 = 0.f, l1 = 0.f;
    float oacc[16][4];
    #pragma unroll
    for (int j = 0; j < 16; j++)
        #pragma unroll
        for (int c = 0; c < 4; c++) oacc[j][c] = 0.f;

    for (int blk = 0; blk < 32; blk++) {
        __syncthreads();   // prev compute done reading KV (and Q store on blk 0)
        {
            const int s0 = blk * 32;
            // 32 rows x 128 cols: 1024 float4 chunks / 256 threads = 4 each (K) + 4 (V)
            #pragma unroll
            for (int i = 0; i < 4; i++) {
                int f = tid + i * 256;
                int r = f >> 5, c4 = (f & 31) << 2;
                float4 a = *(const float4*)(Kg + (size_t)(s0 + r) * (NKV * HD) + c4);
                uint32_t h01, l01, h23, l23;
                bf16_split2(a.x, a.y, h01, l01);
                bf16_split2(a.z, a.w, h23, l23);
                int off = (r * 136 + c4) << 1;
                *(uint2*)(smraw + A_KH + off) = make_uint2(h01, h23);
                *(uint2*)(smraw + A_KL + off) = make_uint2(l01, l23);
                float4 vv = *(const float4*)(Vg + (size_t)(s0 + r) * (NKV * HD) + c4);
                *(uint2*)(smraw + A_VS + ((r * VSH + c4) << 1)) =
                    make_uint2(fp16_pack2(vv.x, vv.y), fp16_pack2(vv.z, vv.w));
            }
        }
        __syncthreads();

        // ---- S = Q K^T (3-pass bf16), 4 n-tiles of 8 keys ----
        float sacc[4][4];
        #pragma unroll
        for (int j = 0; j < 4; j++)
            #pragma unroll
            for (int c = 0; c < 4; c++) sacc[j][c] = 0.f;

        #pragma unroll
        for (int kk = 0; kk < 8; kk++) {
            const int col0h = kk * 16;
            uint32_t ah[4], al[4];
            {
                int m = wm + (lane & 15);
                uint32_t ab = sb + A_QH + ((m * 136 + col0h + ((lane >> 4) << 3)) << 1);
                ldsm_x4(ah, ab);
                ldsm_x4(al, ab + (A_QL - A_QH));
            }
            #pragma unroll
            for (int j2 = 0; j2 < 2; j2++) {
                int row = (j2 * 2 + (lane >> 4)) * 8 + (lane & 7);
                uint32_t bb = sb + A_KH + ((row * 136 + col0h + (lane & 8)) << 1);
                uint32_t bh4[4], bl4[4];
                ldsm_x4(bh4, bb);
                ldsm_x4(bl4, bb + (A_KL - A_KH));
                mma_bf16(sacc[2*j2],   ah, bh4);
                mma_bf16(sacc[2*j2],   ah, bl4);
                mma_bf16(sacc[2*j2],   al, bh4);
                mma_bf16(sacc[2*j2+1], ah, bh4 + 2);
                mma_bf16(sacc[2*j2+1], ah, bl4 + 2);
                mma_bf16(sacc[2*j2+1], al, bh4 + 2);
            }
        }

        // ---- online softmax (rows grp / grp+8, quad-wide) ----
        float mx0 = -1e30f, mx1 = -1e30f;
        #pragma unroll
        for (int j = 0; j < 4; j++) {
            mx0 = fmaxf(mx0, fmaxf(sacc[j][0], sacc[j][1]));
            mx1 = fmaxf(mx1, fmaxf(sacc[j][2], sacc[j][3]));
        }
        #pragma unroll
        for (int off = 1; off < 4; off <<= 1) {
            mx0 = fmaxf(mx0, __shfl_xor_sync(0xffffffffu, mx0, off));
            mx1 = fmaxf(mx1, __shfl_xor_sync(0xffffffffu, mx1, off));
        }
        float mn0 = fmaxf(m0, mx0), mn1 = fmaxf(m1, mx1);
        float cr0 = __expf(m0 - mn0), cr1 = __expf(m1 - mn1);
        float ps0 = 0.f, ps1 = 0.f;
        uint32_t pk[4][2];   // packed fp16 P fragments, straight from registers
        #pragma unroll
        for (int j = 0; j < 4; j++) {
            float e0 = __expf(sacc[j][0] - mn0);
            float e1 = __expf(sacc[j][1] - mn0);
            float e2 = __expf(sacc[j][2] - mn1);
            float e3 = __expf(sacc[j][3] - mn1);
            ps0 += e0 + e1; ps1 += e2 + e3;
            pk[j][0] = fp16_pack2(e0, e1);
            pk[j][1] = fp16_pack2(e2, e3);
        }
        #pragma unroll
        for (int off = 1; off < 4; off <<= 1) {
            ps0 += __shfl_xor_sync(0xffffffffu, ps0, off);
            ps1 += __shfl_xor_sync(0xffffffffu, ps1, off);
        }
        l0 = l0 * cr0 + ps0; m0 = mn0;
        l1 = l1 * cr1 + ps1; m1 = mn1;
        #pragma unroll
        for (int j = 0; j < 16; j++) {
            oacc[j][0] *= cr0; oacc[j][1] *= cr0;
            oacc[j][2] *= cr1; oacc[j][3] *= cr1;
        }

        // ---- O += P V (fp16; A from registers, V via ldsm.x4.trans) ----
        #pragma unroll
        for (int kk2 = 0; kk2 < 2; kk2++) {
            uint32_t pa[4] = { pk[2*kk2][0], pk[2*kk2][1], pk[2*kk2+1][0], pk[2*kk2+1][1] };
            #pragma unroll
            for (int j2 = 0; j2 < 8; j2++) {
                int kr  = kk2 * 16 + (lane & 15);
                int col = (j2 * 2 + (lane >> 4)) * 8;
                uint32_t vb4[4];
                ldsm_x4t(vb4, sb + A_VS + ((kr * VSH + col) << 1));
                mma_fp16(oacc[2*j2],     pa, vb4);
                mma_fp16(oacc[2*j2 + 1], pa, vb4 + 2);
            }
        }
    }

    // ---- epilogue ----
    float inv0 = 1.0f / l0, inv1 = 1.0f / l1;
    float* o0 = o + ((size_t)(b * T_ + t0 + wm + grp)     * NQ + n) * HD;
    float* o1 = o + ((size_t)(b * T_ + t0 + wm + grp + 8) * NQ + n) * HD;
    #pragma unroll
    for (int j = 0; j < 16; j++) {
        int col = j * 8 + 2 * qid;
        *(float2*)(o0 + col) = make_float2(oacc[j][0] * inv0, oacc[j][1] * inv0);
        *(float2*)(o1 + col) = make_float2(oacc[j][2] * inv1, oacc[j][3] * inv1);
    }
}

// ---------------- Launch ----------------
extern "C" void kernel_launch(void* const* d_in, const int* in_sizes, int n_in,
                              void* d_out, int out_size)
{
    const float* Xq  = (const float*)d_in[0];
    const float* Xkv = (const float*)d_in[1];
    const int*   qpos = (const int*)d_in[2];
    const int*   kpos = (const int*)d_in[3];
    const float* Wq  = (const float*)d_in[4];
    const float* Wk  = (const float*)d_in[5];
    const float* Wv  = (const float*)d_in[6];
    const float* Wo  = (const float*)d_in[7];
    float* out = (float*)d_out;

    float *qb, *kb, *vb, *ab;
    cudaGetSymbolAddress((void**)&qb, g_q);
    cudaGetSymbolAddress((void**)&kb, g_k);
    cudaGetSymbolAddress((void**)&vb, g_v);
    cudaGetSymbolAddress((void**)&ab, g_attn);

    const int P_SMEM = 37888;
    const int O_SMEM = 18944;
    cudaFuncSetAttribute(proj_qkv, cudaFuncAttributeMaxDynamicSharedMemorySize, P_SMEM);
    cudaFuncSetAttribute(gemm_o, cudaFuncAttributeMaxDynamicSharedMemorySize, O_SMEM);
    cudaFuncSetAttribute(attn_tc_kernel, cudaFuncAttributeMaxDynamicSharedMemorySize, A_SMEM);

    // Q/K/V projections in one launch
    proj_qkv<<<dim3(24, 16), 256, P_SMEM>>>(Xq, Wq, qb, Xkv, Wk, kb, Wv, vb);

    // RoPE on q and k
    rope_kernel<<<(B_*T_*NQ*64 + 255) / 256, 256>>>(qb, qpos, B_*T_*NQ*64, NQ);
    rope_kernel<<<(B_*S_*NKV*64 + 255) / 256, 256>>>(kb, kpos, B_*S_*NKV*64, NKV);

    // Attention (occ-2 flash, bf16 QK^T / fp16 PV from registers)
    attn_tc_kernel<<<dim3(T_/128, NQ, B_), 256, A_SMEM>>>(qb, kb, vb, ab);

    // Output projection
    gemm_o<<<dim3(16, 16), 256, O_SMEM>>>(ab, Wo, out);
}

// round 9
// speedup vs baseline: 4.5949x; 1.1061x over previous
#include <cuda_runtime.h>
#include <cuda_bf16.h>
#include <cuda_fp16.h>
#include <cstdint>

#define B_  2
#define T_  1024
#define S_  1024
#define NQ  16
#define NKV 4
#define HD  128

// Scratch (allocation-free rule: __device__ globals)
__device__ float g_q[B_*T_*NQ*HD];      // (B,T,NQ,HD)
__device__ float g_k[B_*S_*NKV*HD];     // (B,S,NKV,HD)
__device__ float g_v[B_*S_*NKV*HD];
__device__ float g_attn[B_*T_*NQ*HD];

// ---------------------------------------------------------------------------
// helpers
// ---------------------------------------------------------------------------
__device__ __forceinline__ void mma_bf16(float d[4], const uint32_t a[4], const uint32_t b[2]) {
    asm volatile(
        "mma.sync.aligned.m16n8k16.row.col.f32.bf16.bf16.f32 "
        "{%0,%1,%2,%3}, {%4,%5,%6,%7}, {%8,%9}, {%0,%1,%2,%3};\n"
        : "+f"(d[0]), "+f"(d[1]), "+f"(d[2]), "+f"(d[3])
        : "r"(a[0]), "r"(a[1]), "r"(a[2]), "r"(a[3]), "r"(b[0]), "r"(b[1]));
}
__device__ __forceinline__ void mma_fp16(float d[4], const uint32_t a[4], const uint32_t b[2]) {
    asm volatile(
        "mma.sync.aligned.m16n8k16.row.col.f32.f16.f16.f32 "
        "{%0,%1,%2,%3}, {%4,%5,%6,%7}, {%8,%9}, {%0,%1,%2,%3};\n"
        : "+f"(d[0]), "+f"(d[1]), "+f"(d[2]), "+f"(d[3])
        : "r"(a[0]), "r"(a[1]), "r"(a[2]), "r"(a[3]), "r"(b[0]), "r"(b[1]));
}
__device__ __forceinline__ void ldsm_x4(uint32_t r[4], uint32_t addr) {
    asm volatile("ldmatrix.sync.aligned.m8n8.x4.shared.b16 {%0,%1,%2,%3}, [%4];"
                 : "=r"(r[0]), "=r"(r[1]), "=r"(r[2]), "=r"(r[3]) : "r"(addr));
}
__device__ __forceinline__ void ldsm_x4t(uint32_t r[4], uint32_t addr) {
    asm volatile("ldmatrix.sync.aligned.m8n8.x4.trans.shared.b16 {%0,%1,%2,%3}, [%4];"
                 : "=r"(r[0]), "=r"(r[1]), "=r"(r[2]), "=r"(r[3]) : "r"(addr));
}
__device__ __forceinline__ void ldsm_x2t(uint32_t r[2], uint32_t addr) {
    asm volatile("ldmatrix.sync.aligned.m8n8.x2.trans.shared.b16 {%0,%1}, [%2];"
                 : "=r"(r[0]), "=r"(r[1]) : "r"(addr));
}
__device__ __forceinline__ void bf16_split2(float x, float y, uint32_t& hi, uint32_t& lo) {
    __nv_bfloat16 hx = __float2bfloat16(x);
    __nv_bfloat16 hy = __float2bfloat16(y);
    __nv_bfloat16 lx = __float2bfloat16(x - __bfloat162float(hx));
    __nv_bfloat16 ly = __float2bfloat16(y - __bfloat162float(hy));
    hi = (uint32_t)__bfloat16_as_ushort(hx) | ((uint32_t)__bfloat16_as_ushort(hy) << 16);
    lo = (uint32_t)__bfloat16_as_ushort(lx) | ((uint32_t)__bfloat16_as_ushort(ly) << 16);
}
__device__ __forceinline__ uint32_t fp16_pack2(float x, float y) {
    __half2 h = __floats2half2_rn(x, y);
    return *(uint32_t*)&h;
}

// ---------------------------------------------------------------------------
// GEMM core: C[M,N] = A[M,K] @ B[K,N], CTA 128x128, BK=32, 8 warps 2x4.
// PASSES=3: bf16 hi/lo 3-term split. PASSES=1: 1-pass fp16.
// ---------------------------------------------------------------------------
template<int PASSES>
__device__ __forceinline__ void gemm_core(
    const float* __restrict__ A, const float* __restrict__ Bm, float* __restrict__ C,
    int N, int K, int row0, int col0, char* smraw)
{
    const uint32_t sb = (uint32_t)__cvta_generic_to_shared(smraw);
    constexpr int AHo = 0;
    constexpr int ALo = 10240;
    constexpr int BHo = (PASSES == 3) ? 20480 : 10240;
    constexpr int BLo = 29184;

    const int tid  = threadIdx.x;
    const int lane = tid & 31;
    const int warp = tid >> 5;
    const int grp  = lane >> 2;
    const int qid  = lane & 3;
    const int wm   = (warp >> 2) * 64;
    const int wn   = (warp & 3) * 32;

    float acc[4][4][4];
    #pragma unroll
    for (int i = 0; i < 4; i++)
        #pragma unroll
        for (int j = 0; j < 4; j++)
            #pragma unroll
            for (int c = 0; c < 4; c++) acc[i][j][c] = 0.f;

    float4 aReg[4], bReg[4];
    #pragma unroll
    for (int i = 0; i < 4; i++) {
        int idx = tid + i * 256;
        int ar = idx >> 3, ac = (idx & 7) << 2;
        aReg[i] = *(const float4*)(A + (size_t)(row0 + ar) * K + ac);
        int bk = idx >> 5, bn = (idx & 31) << 2;
        bReg[i] = *(const float4*)(Bm + (size_t)bk * N + col0 + bn);
    }

    for (int k0 = 0; k0 < K; k0 += 32) {
        #pragma unroll
        for (int i = 0; i < 4; i++) {
            int idx = tid + i * 256;
            int ar = idx >> 3, ac = (idx & 7) << 2;
            int aoff = (ar * 40 + ac) << 1;
            int bk = idx >> 5, bn = (idx & 31) << 2;
            int boff = (bk * 136 + bn) << 1;
            if (PASSES == 3) {
                uint32_t h01, l01, h23, l23;
                bf16_split2(aReg[i].x, aReg[i].y, h01, l01);
                bf16_split2(aReg[i].z, aReg[i].w, h23, l23);
                *(uint2*)(smraw + AHo + aoff) = make_uint2(h01, h23);
                *(uint2*)(smraw + ALo + aoff) = make_uint2(l01, l23);
                bf16_split2(bReg[i].x, bReg[i].y, h01, l01);
                bf16_split2(bReg[i].z, bReg[i].w, h23, l23);
                *(uint2*)(smraw + BHo + boff) = make_uint2(h01, h23);
                *(uint2*)(smraw + BLo + boff) = make_uint2(l01, l23);
            } else {
                *(uint2*)(smraw + AHo + aoff) =
                    make_uint2(fp16_pack2(aReg[i].x, aReg[i].y), fp16_pack2(aReg[i].z, aReg[i].w));
                *(uint2*)(smraw + BHo + boff) =
                    make_uint2(fp16_pack2(bReg[i].x, bReg[i].y), fp16_pack2(bReg[i].z, bReg[i].w));
            }
        }
        __syncthreads();

        if (k0 + 32 < K) {
            #pragma unroll
            for (int i = 0; i < 4; i++) {
                int idx = tid + i * 256;
                int ar = idx >> 3, ac = (idx & 7) << 2;
                aReg[i] = *(const float4*)(A + (size_t)(row0 + ar) * K + k0 + 32 + ac);
                int bk = idx >> 5, bn = (idx & 31) << 2;
                bReg[i] = *(const float4*)(Bm + (size_t)(k0 + 32 + bk) * N + col0 + bn);
            }
        }

        #pragma unroll
        for (int kk = 0; kk < 32; kk += 16) {
            uint32_t ah[4][4], al[4][4];
            #pragma unroll
            for (int im = 0; im < 4; im++) {
                int m = wm + im * 16 + (lane & 15);
                uint32_t ab = sb + AHo + ((m * 40 + kk + ((lane >> 4) << 3)) << 1);
                ldsm_x4(ah[im], ab);
                if (PASSES == 3) ldsm_x4(al[im], ab + (ALo - AHo));
            }
            uint32_t bh[4][2], bl[4][2];
            #pragma unroll
            for (int in_ = 0; in_ < 4; in_++) {
                int kr = kk + (lane & 15);
                uint32_t bb = sb + BHo + ((kr * 136 + wn + in_ * 8) << 1);
                ldsm_x2t(bh[in_], bb);
                if (PASSES == 3) ldsm_x2t(bl[in_], bb + (BLo - BHo));
            }
            #pragma unroll
            for (int im = 0; im < 4; im++)
                #pragma unroll
                for (int in_ = 0; in_ < 4; in_++) {
                    if (PASSES == 3) {
                        mma_bf16(acc[im][in_], ah[im], bh[in_]);
                        mma_bf16(acc[im][in_], ah[im], bl[in_]);
                        mma_bf16(acc[im][in_], al[im], bh[in_]);
                    } else {
                        mma_fp16(acc[im][in_], ah[im], bh[in_]);
                    }
                }
        }
        __syncthreads();
    }

    #pragma unroll
    for (int im = 0; im < 4; im++) {
        int r = row0 + wm + im * 16 + grp;
        #pragma unroll
        for (int in_ = 0; in_ < 4; in_++) {
            int nc = col0 + wn + in_ * 8 + 2 * qid;
            *(float2*)(C + (size_t)r * N + nc)       = make_float2(acc[im][in_][0], acc[im][in_][1]);
            *(float2*)(C + (size_t)(r + 8) * N + nc) = make_float2(acc[im][in_][2], acc[im][in_][3]);
        }
    }
}

// Merged Q/K/V projections, occ-2.
__global__ void __launch_bounds__(256, 2) proj_qkv(
    const float* __restrict__ Xq, const float* __restrict__ Wq, float* __restrict__ Cq,
    const float* __restrict__ Xkv, const float* __restrict__ Wk, float* __restrict__ Ck,
    const float* __restrict__ Wv, float* __restrict__ Cv)
{
    extern __shared__ char smraw[];
    const int bx = blockIdx.x;
    const int row0 = blockIdx.y * 128;
    if (bx < 16)
        gemm_core<3>(Xq, Wq, Cq, 2048, 2048, row0, bx * 128, smraw);
    else if (bx < 20)
        gemm_core<3>(Xkv, Wk, Ck, 512, 2048, row0, (bx - 16) * 128, smraw);
    else
        gemm_core<1>(Xkv, Wv, Cv, 512, 2048, row0, (bx - 20) * 128, smraw);
}

// Output projection (fp16 1-pass), occ-2.
__global__ void __launch_bounds__(256, 2) gemm_o(
    const float* __restrict__ A, const float* __restrict__ Bm, float* __restrict__ C)
{
    extern __shared__ char smraw[];
    gemm_core<1>(A, Bm, C, 2048, 2048, blockIdx.y * 128, blockIdx.x * 128, smraw);
}

// ---------------- RoPE fused (q then k ranges in one grid) ----------------
#define QROPE_TOTAL (B_*T_*NQ*64)
#define KROPE_TOTAL (B_*S_*NKV*64)

__global__ void rope_fused(float* __restrict__ xq, float* __restrict__ xk,
                           const int* __restrict__ qpos, const int* __restrict__ kpos)
{
    int idx = blockIdx.x * blockDim.x + threadIdx.x;
    float* x;
    const int* pos;
    int Nh;
    if (idx < QROPE_TOTAL) {
        x = xq; pos = qpos; Nh = NQ;
    } else {
        idx -= QROPE_TOTAL;
        if (idx >= KROPE_TOTAL) return;
        x = xk; pos = kpos; Nh = NKV;
    }
    int i   = idx & 63;
    int bln = idx >> 6;
    int bl  = bln / Nh;
    float p    = (float)pos[bl];
    float frac = (float)i * (1.0f / 64.0f);
    float ts   = powf(10000.0f, frac);
    float ang  = p / ts;
    float si = sinf(ang), co = cosf(ang);
    float* base = x + (size_t)bln * HD;
    float x1 = base[i], x2 = base[i + 64];
    base[i]      = x1 * co - x2 * si;
    base[i + 64] = x2 * co + x1 * si;
}

// ---------------------------------------------------------------------------
// Flash attention (unchanged from R8): occ-2, KV block 32, bf16-3x QK^T,
// fp16 PV with register-built A fragments.
// ---------------------------------------------------------------------------
#define A_QH 0
#define A_QL 34816
#define A_KH 69632
#define A_KL 78336
#define A_VS 87040
#define A_SMEM 95744
#define VSH 136

__global__ void __launch_bounds__(256, 2) attn_tc_kernel(
    const float* __restrict__ q, const float* __restrict__ k,
    const float* __restrict__ v, float* __restrict__ o)
{
    extern __shared__ char smraw[];
    const uint32_t sb = (uint32_t)__cvta_generic_to_shared(smraw);

    const int tid  = threadIdx.x;
    const int lane = tid & 31;
    const int warp = tid >> 5;
    const int grp  = lane >> 2;
    const int qid  = lane & 3;
    const int wm   = warp * 16;
    const int t0   = blockIdx.x * 128;
    const int n    = blockIdx.y;
    const int b    = blockIdx.z;
    const int kvh  = n >> 2;

    const float* Qg = q + ((size_t)(b * T_ + t0) * NQ  + n)   * HD;
    const float* Kg = k + ((size_t)(b * S_)      * NKV + kvh) * HD;
    const float* Vg = v + ((size_t)(b * S_)      * NKV + kvh) * HD;

    for (int f = tid; f < 128 * 32; f += 256) {
        int r = f >> 5, c4 = (f & 31) << 2;
        float4 a = *(const float4*)(Qg + (size_t)r * (NQ * HD) + c4);
        uint32_t h01, l01, h23, l23;
        bf16_split2(a.x, a.y, h01, l01);
        bf16_split2(a.z, a.w, h23, l23);
        int off = (r * 136 + c4) << 1;
        *(uint2*)(smraw + A_QH + off) = make_uint2(h01, h23);
        *(uint2*)(smraw + A_QL + off) = make_uint2(l01, l23);
    }

    float m0 = -1e30f, m1 = -1e30f, l0 = 0.f, l1 = 0.f;
    float oacc[16][4];
    #pragma unroll
    for (int j = 0; j < 16; j++)
        #pragma unroll
        for (int c = 0; c < 4; c++) oacc[j][c] = 0.f;

    for (int blk = 0; blk < 32; blk++) {
        __syncthreads();
        {
            const int s0 = blk * 32;
            #pragma unroll
            for (int i = 0; i < 4; i++) {
                int f = tid + i * 256;
                int r = f >> 5, c4 = (f & 31) << 2;
                float4 a = *(const float4*)(Kg + (size_t)(s0 + r) * (NKV * HD) + c4);
                uint32_t h01, l01, h23, l23;
                bf16_split2(a.x, a.y, h01, l01);
                bf16_split2(a.z, a.w, h23, l23);
                int off = (r * 136 + c4) << 1;
                *(uint2*)(smraw + A_KH + off) = make_uint2(h01, h23);
                *(uint2*)(smraw + A_KL + off) = make_uint2(l01, l23);
                float4 vv = *(const float4*)(Vg + (size_t)(s0 + r) * (NKV * HD) + c4);
                *(uint2*)(smraw + A_VS + ((r * VSH + c4) << 1)) =
                    make_uint2(fp16_pack2(vv.x, vv.y), fp16_pack2(vv.z, vv.w));
            }
        }
        __syncthreads();

        float sacc[4][4];
        #pragma unroll
        for (int j = 0; j < 4; j++)
            #pragma unroll
            for (int c = 0; c < 4; c++) sacc[j][c] = 0.f;

        #pragma unroll
        for (int kk = 0; kk < 8; kk++) {
            const int col0h = kk * 16;
            uint32_t ah[4], al[4];
            {
                int m = wm + (lane & 15);
                uint32_t ab = sb + A_QH + ((m * 136 + col0h + ((lane >> 4) << 3)) << 1);
                ldsm_x4(ah, ab);
                ldsm_x4(al, ab + (A_QL - A_QH));
            }
            #pragma unroll
            for (int j2 = 0; j2 < 2; j2++) {
                int row = (j2 * 2 + (lane >> 4)) * 8 + (lane & 7);
                uint32_t bb = sb + A_KH + ((row * 136 + col0h + (lane & 8)) << 1);
                uint32_t bh4[4], bl4[4];
                ldsm_x4(bh4, bb);
                ldsm_x4(bl4, bb + (A_KL - A_KH));
                mma_bf16(sacc[2*j2],   ah, bh4);
                mma_bf16(sacc[2*j2],   ah, bl4);
                mma_bf16(sacc[2*j2],   al, bh4);
                mma_bf16(sacc[2*j2+1], ah, bh4 + 2);
                mma_bf16(sacc[2*j2+1], ah, bl4 + 2);
                mma_bf16(sacc[2*j2+1], al, bh4 + 2);
            }
        }

        float mx0 = -1e30f, mx1 = -1e30f;
        #pragma unroll
        for (int j = 0; j < 4; j++) {
            mx0 = fmaxf(mx0, fmaxf(sacc[j][0], sacc[j][1]));
            mx1 = fmaxf(mx1, fmaxf(sacc[j][2], sacc[j][3]));
        }
        #pragma unroll
        for (int off = 1; off < 4; off <<= 1) {
            mx0 = fmaxf(mx0, __shfl_xor_sync(0xffffffffu, mx0, off));
            mx1 = fmaxf(mx1, __shfl_xor_sync(0xffffffffu, mx1, off));
        }
        float mn0 = fmaxf(m0, mx0), mn1 = fmaxf(m1, mx1);
        float cr0 = __expf(m0 - mn0), cr1 = __expf(m1 - mn1);
        float ps0 = 0.f, ps1 = 0.f;
        uint32_t pk[4][2];
        #pragma unroll
        for (int j = 0; j < 4; j++) {
            float e0 = __expf(sacc[j][0] - mn0);
            float e1 = __expf(sacc[j][1] - mn0);
            float e2 = __expf(sacc[j][2] - mn1);
            float e3 = __expf(sacc[j][3] - mn1);
            ps0 += e0 + e1; ps1 += e2 + e3;
            pk[j][0] = fp16_pack2(e0, e1);
            pk[j][1] = fp16_pack2(e2, e3);
        }
        #pragma unroll
        for (int off = 1; off < 4; off <<= 1) {
            ps0 += __shfl_xor_sync(0xffffffffu, ps0, off);
            ps1 += __shfl_xor_sync(0xffffffffu, ps1, off);
        }
        l0 = l0 * cr0 + ps0; m0 = mn0;
        l1 = l1 * cr1 + ps1; m1 = mn1;
        #pragma unroll
        for (int j = 0; j < 16; j++) {
            oacc[j][0] *= cr0; oacc[j][1] *= cr0;
            oacc[j][2] *= cr1; oacc[j][3] *= cr1;
        }

        #pragma unroll
        for (int kk2 = 0; kk2 < 2; kk2++) {
            uint32_t pa[4] = { pk[2*kk2][0], pk[2*kk2][1], pk[2*kk2+1][0], pk[2*kk2+1][1] };
            #pragma unroll
            for (int j2 = 0; j2 < 8; j2++) {
                int kr  = kk2 * 16 + (lane & 15);
                int col = (j2 * 2 + (lane >> 4)) * 8;
                uint32_t vb4[4];
                ldsm_x4t(vb4, sb + A_VS + ((kr * VSH + col) << 1));
                mma_fp16(oacc[2*j2],     pa, vb4);
                mma_fp16(oacc[2*j2 + 1], pa, vb4 + 2);
            }
        }
    }

    float inv0 = 1.0f / l0, inv1 = 1.0f / l1;
    float* o0 = o + ((size_t)(b * T_ + t0 + wm + grp)     * NQ + n) * HD;
    float* o1 = o + ((size_t)(b * T_ + t0 + wm + grp + 8) * NQ + n) * HD;
    #pragma unroll
    for (int j = 0; j < 16; j++) {
        int col = j * 8 + 2 * qid;
        *(float2*)(o0 + col) = make_float2(oacc[j][0] * inv0, oacc[j][1] * inv0);
        *(float2*)(o1 + col) = make_float2(oacc[j][2] * inv1, oacc[j][3] * inv1);
    }
}

// ---------------- Launch ----------------
extern "C" void kernel_launch(void* const* d_in, const int* in_sizes, int n_in,
                              void* d_out, int out_size)
{
    const float* Xq  = (const float*)d_in[0];
    const float* Xkv = (const float*)d_in[1];
    const int*   qpos = (const int*)d_in[2];
    const int*   kpos = (const int*)d_in[3];
    const float* Wq  = (const float*)d_in[4];
    const float* Wk  = (const float*)d_in[5];
    const float* Wv  = (const float*)d_in[6];
    const float* Wo  = (const float*)d_in[7];
    float* out = (float*)d_out;

    float *qb, *kb, *vb, *ab;
    cudaGetSymbolAddress((void**)&qb, g_q);
    cudaGetSymbolAddress((void**)&kb, g_k);
    cudaGetSymbolAddress((void**)&vb, g_v);
    cudaGetSymbolAddress((void**)&ab, g_attn);

    const int P_SMEM = 37888;
    const int O_SMEM = 18944;
    cudaFuncSetAttribute(proj_qkv, cudaFuncAttributeMaxDynamicSharedMemorySize, P_SMEM);
    cudaFuncSetAttribute(gemm_o, cudaFuncAttributeMaxDynamicSharedMemorySize, O_SMEM);
    cudaFuncSetAttribute(attn_tc_kernel, cudaFuncAttributeMaxDynamicSharedMemorySize, A_SMEM);

    // Q/K/V projections in one launch (occ-2)
    proj_qkv<<<dim3(24, 16), 256, P_SMEM>>>(Xq, Wq, qb, Xkv, Wk, kb, Wv, vb);

    // RoPE on q and k, one launch
    rope_fused<<<(QROPE_TOTAL + KROPE_TOTAL + 255) / 256, 256>>>(qb, kb, qpos, kpos);

    // Attention (occ-2 flash, bf16 QK^T / fp16 PV from registers)
    attn_tc_kernel<<<dim3(T_/128, NQ, B_), 256, A_SMEM>>>(qb, kb, vb, ab);

    // Output projection (occ-2)
    gemm_o<<<dim3(16, 16), 256, O_SMEM>>>(ab, Wo, out);
}